// round 14
// baseline (speedup 1.0000x reference)
#include <cuda_runtime.h>
#include <cuda_bf16.h>
#include <cuda_fp16.h>
#include <math.h>
#include <stdint.h>

// ---------------------------------------------------------------------------
// downprompt. R14: full FP8 pipeline — e4m3 x e4m3 QMMA (m16n8k32) GEMMs,
// all activations e4m3, fp32 accum/epilogues. Gather (fp8->HFMA2) and
// side-stream CSR build from R13. Dead-e3 eliminated.
// ---------------------------------------------------------------------------

#define DD   256
#define MAXN 20000
#define MAXE 320000
#define MAXM 2048
#define NC   10

typedef __nv_bfloat16 bf16;
typedef __nv_bfloat162 bf162;

__device__ uint8_t g_x8 [MAXN * DD];     // current x (e4m3)
__device__ uint8_t g_x08[MAXN * DD];     // origin x (e4m3)
__device__ uint8_t g_h8 [MAXN * DD];     // GEMM out / CN hidden (e4m3)
__device__ uint8_t g_e18[MAXN * DD];
__device__ uint8_t g_e28[MAXN * DD];
__device__ uint32_t g_wq[12 * 16384];    // 12 weights, e4m3 k-quads [k4][n]
__device__ int   g_degi[MAXN];
__device__ float g_dinv[MAXN];
__device__ float g_invdeg[MAXN];
__device__ int   g_rowptr[MAXN + 4];
__device__ int   g_cursor[MAXN + 4];
__device__ int2  g_epack[MAXE];
__device__ float g_raw[MAXM * DD];
__device__ float g_sums[NC * DD + 32];
__device__ float g_an[NC * DD];

struct StreamInit {
    cudaStream_t s2 = nullptr;
    cudaEvent_t ev1 = nullptr, ev2 = nullptr;
    bool ok = false;
    StreamInit() {
        ok = (cudaStreamCreateWithFlags(&s2, cudaStreamNonBlocking) == cudaSuccess) &&
             (cudaEventCreateWithFlags(&ev1, cudaEventDisableTiming) == cudaSuccess) &&
             (cudaEventCreateWithFlags(&ev2, cudaEventDisableTiming) == cudaSuccess);
    }
};
static StreamInit g_si;

__device__ __forceinline__ float warp_sum(float v) {
#pragma unroll
    for (int o = 16; o > 0; o >>= 1) v += __shfl_xor_sync(0xffffffffu, v, o);
    return v;
}

__device__ __forceinline__ void mma_fp8(
    float& c0, float& c1, float& c2, float& c3,
    uint32_t a0, uint32_t a1, uint32_t a2, uint32_t a3,
    uint32_t b0, uint32_t b1)
{
    asm volatile(
        "mma.sync.aligned.m16n8k32.row.col.f32.e4m3.e4m3.f32 "
        "{%0,%1,%2,%3},{%4,%5,%6,%7},{%8,%9},{%0,%1,%2,%3};"
        : "+f"(c0), "+f"(c1), "+f"(c2), "+f"(c3)
        : "r"(a0), "r"(a1), "r"(a2), "r"(a3), "r"(b0), "r"(b1));
}

__device__ __forceinline__ void cp_async16(void* smem_dst, const void* gmem_src, int src_bytes) {
    uint32_t s = (uint32_t)__cvta_generic_to_shared(smem_dst);
    asm volatile("cp.async.cg.shared.global [%0], [%1], 16, %2;"
                 :: "r"(s), "l"(gmem_src), "r"(src_bytes));
}

__device__ __forceinline__ unsigned short f2_e4m3x2(float lo, float hi) {
    unsigned short p;
    asm("cvt.rn.satfinite.e4m3x2.f32 %0, %1, %2;" : "=h"(p) : "f"(hi), "f"(lo));
    return p;
}

// ---------------------------------------------------------------------------
// Weight prepack: wq[m][k4*256+n] = e4m3(W[4k4+0..3][n]) packed in uint32.
// ---------------------------------------------------------------------------
__global__ void __launch_bounds__(256) prepack_weights_fp8(
    const float* __restrict__ W1, const float* __restrict__ W2,
    const float* __restrict__ W3, const float* __restrict__ cw_in,
    const float* __restrict__ cw_hid, const float* __restrict__ cw_out,
    uint32_t* __restrict__ wq)
{
    int m = blockIdx.y;
    const float* W =
        (m == 0) ? W1 : (m == 1) ? W2 : (m == 2) ? W3 :
        (m < 6) ? cw_in  + (size_t)(m - 3) * 65536 :
        (m < 9) ? cw_hid + (size_t)(m - 6) * 65536 :
                  cw_out + (size_t)(m - 9) * 65536;
    int i = blockIdx.x * 256 + threadIdx.x;    // k4*256 + n, 64*256 entries
    int k4 = i >> 8, n = i & 255;
    float v0 = W[(size_t)(4 * k4 + 0) * 256 + n];
    float v1 = W[(size_t)(4 * k4 + 1) * 256 + n];
    float v2 = W[(size_t)(4 * k4 + 2) * 256 + n];
    float v3 = W[(size_t)(4 * k4 + 3) * 256 + n];
    uint32_t pk = (uint32_t)f2_e4m3x2(v0, v1) | ((uint32_t)f2_e4m3x2(v2, v3) << 16);
    wq[(size_t)m * 16384 + i] = pk;
}

__global__ void __launch_bounds__(256) conv_f32_fp8(
    const float* __restrict__ in, uint8_t* __restrict__ out, int n8)
{
    int i = blockIdx.x * blockDim.x + threadIdx.x;
    if (i >= n8) return;
    float4 a = ((const float4*)in)[2 * i];
    float4 b = ((const float4*)in)[2 * i + 1];
    uint2 u;
    u.x = (uint32_t)f2_e4m3x2(a.x, a.y) | ((uint32_t)f2_e4m3x2(a.z, a.w) << 16);
    u.y = (uint32_t)f2_e4m3x2(b.x, b.y) | ((uint32_t)f2_e4m3x2(b.z, b.w) << 16);
    ((uint2*)out)[i] = u;
}

// ---------------------------------------------------------------------------
// FP8 GEMM: C(e4m3)[N,256] = A(e4m3)[N,256] @ Wq  (+ epilogue, fp32 accum)
// 128x128 tile, BK=64, 2-stage cp.async, 8 warps (4M x 2N), m16n8k32.
// EPI 0: plain. EPI 1: elu(acc+bias). EPI 2: (acc+bias)*extra(e4m3)
// ---------------------------------------------------------------------------
#define A8STR 80     // bytes per A row (64 + 16 pad); uint32 stride 20
#define BQSTR 136    // uint32 per B k4-row (128 + 8 pad)

template <int EPI>
__global__ void __launch_bounds__(256) fp8_gemm(
    const uint8_t* __restrict__ A, const uint32_t* __restrict__ Wq,
    const float* __restrict__ bias, const uint8_t* __restrict__ extra,
    uint8_t* __restrict__ C, int N)
{
    __shared__ __align__(16) uint8_t  As[2][128 * A8STR];
    __shared__ __align__(16) uint32_t Bq[2][16 * BQSTR];

    const int tid  = threadIdx.x;
    const int lane = tid & 31;
    const int wid  = tid >> 5;
    const int wm   = wid & 3;
    const int wn   = wid >> 2;
    const int rowBase = blockIdx.x * 128;
    const int colBase = blockIdx.y * 128;
    const int lq = lane >> 2;
    const int lr = lane & 3;

    float acc[2][8][4];
#pragma unroll
    for (int mt = 0; mt < 2; mt++)
#pragma unroll
        for (int nt = 0; nt < 8; nt++)
#pragma unroll
            for (int i = 0; i < 4; i++) acc[mt][nt][i] = 0.f;

    auto loadTile = [&](int k0, int st) {
#pragma unroll
        for (int i = 0; i < 2; i++) {       // A: 128 rows x 64 B = 512 chunks
            int ch = tid + i * 256;
            int r  = ch >> 2;
            int c16 = (ch & 3) * 16;
            int grow = rowBase + r;
            int ok = (grow < N) ? 16 : 0;
            int crow = (grow < N) ? grow : (N - 1);
            cp_async16(&As[st][r * A8STR + c16], A + (size_t)crow * 256 + k0 + c16, ok);
        }
#pragma unroll
        for (int i = 0; i < 2; i++) {       // B: 16 k4-rows x 128 uint32
            int ch = tid + i * 256;
            int k4 = ch >> 5;
            int nc = (ch & 31) * 4;
            cp_async16(&Bq[st][k4 * BQSTR + nc],
                       Wq + (size_t)(k0 / 4 + k4) * 256 + colBase + nc, 16);
        }
        asm volatile("cp.async.commit_group;");
    };

    loadTile(0, 0);
#pragma unroll
    for (int it = 0; it < 4; it++) {        // K = 256 / 64
        if (it < 3) {
            loadTile((it + 1) * 64, (it + 1) & 1);
            asm volatile("cp.async.wait_group 1;");
        } else {
            asm volatile("cp.async.wait_group 0;");
        }
        __syncthreads();
        const uint8_t*  As_ = As[it & 1];
        const uint32_t* Bp  = Bq[it & 1];
#pragma unroll
        for (int ks = 0; ks < 2; ks++) {    // two k32 steps per BK=64
            uint32_t a[2][4];
#pragma unroll
            for (int mt = 0; mt < 2; mt++) {
                int r = wm * 32 + mt * 16 + lq;
                const uint32_t* ar0 = (const uint32_t*)(As_ + r * A8STR + ks * 32) + lr;
                const uint32_t* ar1 = (const uint32_t*)(As_ + (r + 8) * A8STR + ks * 32) + lr;
                a[mt][0] = ar0[0];
                a[mt][1] = ar1[0];
                a[mt][2] = ar0[4];          // +16 bytes
                a[mt][3] = ar1[4];
            }
            uint32_t b0[8], b1[8];
#pragma unroll
            for (int nt = 0; nt < 8; nt++) {
                int n = wn * 64 + nt * 8 + lq;
                b0[nt] = Bp[(ks * 8 + lr) * BQSTR + n];
                b1[nt] = Bp[(ks * 8 + 4 + lr) * BQSTR + n];
            }
#pragma unroll
            for (int mt = 0; mt < 2; mt++)
#pragma unroll
                for (int nt = 0; nt < 8; nt++)
                    mma_fp8(acc[mt][nt][0], acc[mt][nt][1], acc[mt][nt][2], acc[mt][nt][3],
                            a[mt][0], a[mt][1], a[mt][2], a[mt][3], b0[nt], b1[nt]);
        }
        __syncthreads();
    }

#pragma unroll
    for (int mt = 0; mt < 2; mt++) {
#pragma unroll
        for (int rr = 0; rr < 2; rr++) {
            int row = rowBase + wm * 32 + mt * 16 + lq + rr * 8;
            if (row >= N) continue;
#pragma unroll
            for (int nt = 0; nt < 8; nt++) {
                int col = colBase + wn * 64 + nt * 8 + 2 * lr;
                float v0 = acc[mt][nt][rr * 2 + 0];
                float v1 = acc[mt][nt][rr * 2 + 1];
                if (EPI >= 1) { v0 += bias[col]; v1 += bias[col + 1]; }
                if (EPI == 1) {
                    v0 = v0 > 0.f ? v0 : expm1f(v0);
                    v1 = v1 > 0.f ? v1 : expm1f(v1);
                }
                if (EPI == 2) {
                    unsigned short ex = *(const unsigned short*)(extra + (size_t)row * 256 + col);
                    uint32_t hh;
                    asm("cvt.rn.f16x2.e4m3x2 %0, %1;" : "=r"(hh) : "h"(ex));
                    float2 f = __half22float2(*(__half2*)&hh);
                    v0 *= f.x; v1 *= f.y;
                }
                *(unsigned short*)(C + (size_t)row * 256 + col) = f2_e4m3x2(v0, v1);
            }
        }
    }
}

// ---------------------------------------------------------------------------
// CSR build (side stream)
// ---------------------------------------------------------------------------
__global__ void count_deg(const int* __restrict__ dst, int* __restrict__ degi, int E) {
    int e = blockIdx.x * blockDim.x + threadIdx.x;
    if (e < E) atomicAdd(&degi[dst[e]], 1);
}

__global__ void finalize_deg(const int* __restrict__ degi, float* __restrict__ dinv,
                             float* __restrict__ invdeg, int N) {
    int i = blockIdx.x * blockDim.x + threadIdx.x;
    if (i < N) {
        float d = (float)degi[i] + 1.f;
        dinv[i] = rsqrtf(d);
        invdeg[i] = 1.f / d;
    }
}

__global__ void __launch_bounds__(1024) scan_rowptr(
    const int* __restrict__ degi, int* __restrict__ rowptr, int* __restrict__ cursor, int N)
{
    __shared__ int warpTot[32];
    const int t = threadIdx.x;
    const int lane = t & 31;
    const int warp = t >> 5;
    const int n4 = N >> 2;
    const int per4 = (n4 + 1023) >> 10;
    const int b4 = t * per4;
    const int e4 = min(b4 + per4, n4);
    const int cnt = max(e4 - b4, 0);

    int4 v[8];
    int sum = 0;
    for (int i = 0; i < cnt; i++) {
        v[i] = ((const int4*)degi)[b4 + i];
        sum += v[i].x + v[i].y + v[i].z + v[i].w;
    }

    int inc = sum;
#pragma unroll
    for (int off = 1; off < 32; off <<= 1) {
        int x = __shfl_up_sync(0xffffffffu, inc, off);
        if (lane >= off) inc += x;
    }
    if (lane == 31) warpTot[warp] = inc;
    __syncthreads();
    if (warp == 0) {
        int wv = warpTot[lane];
        int winc = wv;
#pragma unroll
        for (int off = 1; off < 32; off <<= 1) {
            int x = __shfl_up_sync(0xffffffffu, winc, off);
            if (lane >= off) winc += x;
        }
        warpTot[lane] = winc - wv;
    }
    __syncthreads();
    int run = warpTot[warp] + inc - sum;

    for (int i = 0; i < cnt; i++) {
        int base4 = b4 + i;
        int d0 = v[i].x, d1 = v[i].y, d2 = v[i].z, d3 = v[i].w;
        int r0 = run, r1 = r0 + d0, r2 = r1 + d1, r3 = r2 + d2;
        run = r3 + d3;
        int4 rp = make_int4(r0, r1, r2, r3);
        ((int4*)rowptr)[base4] = rp;
        ((int4*)cursor)[base4] = rp;
    }
    if (t == 1023) {
        int run2 = run;
        for (int i = n4 * 4; i < N; i++) {
            rowptr[i] = run2;
            cursor[i] = run2;
            run2 += degi[i];
        }
        rowptr[N] = run2;
    }
}

__global__ void fill_csr(const int* __restrict__ src, const int* __restrict__ dst,
                         const float* __restrict__ dinv, int* __restrict__ cursor,
                         int2* __restrict__ epack, int E)
{
    int e = blockIdx.x * blockDim.x + threadIdx.x;
    if (e >= E) return;
    int s = src[e], d = dst[e];
    int slot = atomicAdd(&cursor[d], 1);
    float cf = dinv[s] * dinv[d];
    __half2 c2 = __float2half2_rn(cf);
    epack[slot] = make_int2(s * DD, (int)*(uint32_t*)&c2);
}

// ---------------------------------------------------------------------------
// Gather SpMM (fp8 in/out), half2 HFMA2 accumulation, packed edges.
// ---------------------------------------------------------------------------
__device__ __forceinline__ void accum_h2(__half2* acc, uint2 v, __half2 c2) {
    uint32_t h0, h1, h2, h3;
    asm("cvt.rn.f16x2.e4m3x2 %0, %1;" : "=r"(h0) : "h"((unsigned short)(v.x & 0xffffu)));
    asm("cvt.rn.f16x2.e4m3x2 %0, %1;" : "=r"(h1) : "h"((unsigned short)(v.x >> 16)));
    asm("cvt.rn.f16x2.e4m3x2 %0, %1;" : "=r"(h2) : "h"((unsigned short)(v.y & 0xffffu)));
    asm("cvt.rn.f16x2.e4m3x2 %0, %1;" : "=r"(h3) : "h"((unsigned short)(v.y >> 16)));
    acc[0] = __hfma2(*(__half2*)&h0, c2, acc[0]);
    acc[1] = __hfma2(*(__half2*)&h1, c2, acc[1]);
    acc[2] = __hfma2(*(__half2*)&h2, c2, acc[2]);
    acc[3] = __hfma2(*(__half2*)&h3, c2, acc[3]);
}

template <int RES, int SCALE, int ELU>
__global__ void __launch_bounds__(256) gather_gcn_fp8(
    const uint8_t* __restrict__ h, const int* __restrict__ rowptr,
    const int2* __restrict__ epack,
    const float* __restrict__ bias, const float* __restrict__ invdeg,
    const uint8_t* __restrict__ res, const float* __restrict__ scale_ptr,
    uint8_t* __restrict__ out, int N)
{
    int d = (blockIdx.x * blockDim.x + threadIdx.x) >> 5;
    int lane = threadIdx.x & 31;
    if (d >= N) return;

    const int eBeg = rowptr[d];
    const int eEnd = rowptr[d + 1];
    const int coff = lane * 8;
    const uint8_t* hbase = h + coff;

    __half2 hacc[4];
    __half2 hz = __float2half2_rn(0.f);
#pragma unroll
    for (int j = 0; j < 4; j++) hacc[j] = hz;

    int e = eBeg;
    for (; e + 7 < eEnd; e += 8) {
        int2  p[8];
        uint2 v[8];
#pragma unroll
        for (int j = 0; j < 8; j++) p[j] = epack[e + j];
#pragma unroll
        for (int j = 0; j < 8; j++) v[j] = *(const uint2*)(hbase + p[j].x);
#pragma unroll
        for (int j = 0; j < 8; j++) accum_h2(hacc, v[j], *(__half2*)&p[j].y);
    }
    for (; e + 1 < eEnd; e += 2) {
        int2 p0 = epack[e], p1 = epack[e + 1];
        uint2 v0 = *(const uint2*)(hbase + p0.x);
        uint2 v1 = *(const uint2*)(hbase + p1.x);
        accum_h2(hacc, v0, *(__half2*)&p0.y);
        accum_h2(hacc, v1, *(__half2*)&p1.y);
    }
    if (e < eEnd) {
        int2 p0 = epack[e];
        uint2 v0 = *(const uint2*)(hbase + p0.x);
        accum_h2(hacc, v0, *(__half2*)&p0.y);
    }

    uint2 vs = *(const uint2*)(hbase + d * DD);
    accum_h2(hacc, vs, __float2half2_rn(invdeg[d]));

    float acc[8];
#pragma unroll
    for (int j = 0; j < 4; j++) {
        float2 f = __half22float2(hacc[j]);
        acc[2 * j] = f.x;
        acc[2 * j + 1] = f.y;
    }
    float4 b0 = ((const float4*)bias)[lane * 2];
    float4 b1 = ((const float4*)bias)[lane * 2 + 1];
    acc[0] += b0.x; acc[1] += b0.y; acc[2] += b0.z; acc[3] += b0.w;
    acc[4] += b1.x; acc[5] += b1.y; acc[6] += b1.z; acc[7] += b1.w;

    if (RES) {
        uint2 rv = *(const uint2*)(res + (size_t)d * DD + coff);
        uint32_t h0, h1, h2, h3;
        asm("cvt.rn.f16x2.e4m3x2 %0, %1;" : "=r"(h0) : "h"((unsigned short)(rv.x & 0xffffu)));
        asm("cvt.rn.f16x2.e4m3x2 %0, %1;" : "=r"(h1) : "h"((unsigned short)(rv.x >> 16)));
        asm("cvt.rn.f16x2.e4m3x2 %0, %1;" : "=r"(h2) : "h"((unsigned short)(rv.y & 0xffffu)));
        asm("cvt.rn.f16x2.e4m3x2 %0, %1;" : "=r"(h3) : "h"((unsigned short)(rv.y >> 16)));
        float2 f0 = __half22float2(*(__half2*)&h0);
        float2 f1 = __half22float2(*(__half2*)&h1);
        float2 f2 = __half22float2(*(__half2*)&h2);
        float2 f3 = __half22float2(*(__half2*)&h3);
        acc[0] += f0.x; acc[1] += f0.y; acc[2] += f1.x; acc[3] += f1.y;
        acc[4] += f2.x; acc[5] += f2.y; acc[6] += f3.x; acc[7] += f3.y;
    }
    if (SCALE) {
        float sc = scale_ptr[0];
#pragma unroll
        for (int j = 0; j < 8; j++) acc[j] *= sc;
    }
    if (ELU) {
#pragma unroll
        for (int j = 0; j < 8; j++) acc[j] = acc[j] > 0.f ? acc[j] : expm1f(acc[j]);
    }
    uint2 ov;
    ov.x = (uint32_t)f2_e4m3x2(acc[0], acc[1]) | ((uint32_t)f2_e4m3x2(acc[2], acc[3]) << 16);
    ov.y = (uint32_t)f2_e4m3x2(acc[4], acc[5]) | ((uint32_t)f2_e4m3x2(acc[6], acc[7]) << 16);
    *(uint2*)(out + (size_t)d * DD + coff) = ov;
}

// ---------------------------------------------------------------------------
// Prompt attention on the M selected rows (e4m3 h). 1 warp / row.
// ---------------------------------------------------------------------------
__global__ void __launch_bounds__(256) embed_select(
    const uint8_t* __restrict__ h, const float* __restrict__ aW,
    const float* __restrict__ ab, const float* __restrict__ p,
    const int* __restrict__ idx, float* __restrict__ raw, int M)
{
    int m = (blockIdx.x * blockDim.x + threadIdx.x) >> 5;
    int lane = threadIdx.x & 31;
    if (m >= M) return;
    int node = idx[m];
    const int coff = lane * 8;
    uint2 hv8 = *(const uint2*)(h + (size_t)node * DD + coff);
    float hv[8];
    {
        uint32_t h0, h1, h2, h3;
        asm("cvt.rn.f16x2.e4m3x2 %0, %1;" : "=r"(h0) : "h"((unsigned short)(hv8.x & 0xffffu)));
        asm("cvt.rn.f16x2.e4m3x2 %0, %1;" : "=r"(h1) : "h"((unsigned short)(hv8.x >> 16)));
        asm("cvt.rn.f16x2.e4m3x2 %0, %1;" : "=r"(h2) : "h"((unsigned short)(hv8.y & 0xffffu)));
        asm("cvt.rn.f16x2.e4m3x2 %0, %1;" : "=r"(h3) : "h"((unsigned short)(hv8.y >> 16)));
        float2 f0 = __half22float2(*(__half2*)&h0);
        float2 f1 = __half22float2(*(__half2*)&h1);
        float2 f2 = __half22float2(*(__half2*)&h2);
        float2 f3 = __half22float2(*(__half2*)&h3);
        hv[0] = f0.x; hv[1] = f0.y; hv[2] = f1.x; hv[3] = f1.y;
        hv[4] = f2.x; hv[5] = f2.y; hv[6] = f3.x; hv[7] = f3.y;
    }
    float lg[5] = {0.f, 0.f, 0.f, 0.f, 0.f};
#pragma unroll
    for (int j = 0; j < 8; j++) {
        int c = coff + j;
#pragma unroll
        for (int k = 0; k < 5; k++) lg[k] += hv[j] * aW[c * 5 + k];
    }
#pragma unroll
    for (int k = 0; k < 5; k++) lg[k] = warp_sum(lg[k]) + ab[k];
    float mx = lg[0];
#pragma unroll
    for (int k = 1; k < 5; k++) mx = fmaxf(mx, lg[k]);
    float wgt[5], s = 0.f;
#pragma unroll
    for (int k = 0; k < 5; k++) { wgt[k] = expf(lg[k] - mx); s += wgt[k]; }
    float inv = 1.f / s;
#pragma unroll
    for (int k = 0; k < 5; k++) wgt[k] *= inv;
#pragma unroll
    for (int j = 0; j < 8; j++) {
        int c = coff + j;
        float v = hv[j];
#pragma unroll
        for (int k = 0; k < 5; k++) v += wgt[k] * p[k * DD + c];
        raw[(size_t)m * DD + c] = v;
    }
}

// ---------------------------------------------------------------------------
// Class prototypes + cosine softmax
// ---------------------------------------------------------------------------
__global__ void __launch_bounds__(256) proto_accum(
    const float* __restrict__ raw, const int* __restrict__ labels, int M)
{
    int m = (blockIdx.x * blockDim.x + threadIdx.x) >> 5;
    int lane = threadIdx.x & 31;
    if (m >= M) return;
    int lab = labels[m];
#pragma unroll
    for (int i = 0; i < 8; i++) {
        int c = lane + 32 * i;
        atomicAdd(&g_sums[lab * DD + c], raw[(size_t)m * DD + c]);
    }
    if (lane == 0) atomicAdd(&g_sums[NC * DD + lab], 1.f);
}

__global__ void an_finalize(const float* __restrict__ sums,
                            const float* __restrict__ cnt, float* __restrict__ an)
{
    int c = blockIdx.x;
    int lane = threadIdx.x;
    float invc = 1.f / fmaxf(cnt[c], 1.f);
    float v[8];
    float ss = 0.f;
#pragma unroll
    for (int i = 0; i < 8; i++) {
        v[i] = sums[c * DD + lane + 32 * i] * invc;
        ss += v[i] * v[i];
    }
    ss = warp_sum(ss);
    float innorm = 1.f / fmaxf(sqrtf(ss), 1e-8f);
#pragma unroll
    for (int i = 0; i < 8; i++) an[c * DD + lane + 32 * i] = v[i] * innorm;
}

__global__ void __launch_bounds__(256) cos_softmax(
    const float* __restrict__ raw, const float* __restrict__ an,
    float* __restrict__ out, int M)
{
    __shared__ float sAn[NC * DD];
    for (int i = threadIdx.x; i < NC * DD; i += 256) sAn[i] = an[i];
    __syncthreads();
    int m = (blockIdx.x * blockDim.x + threadIdx.x) >> 5;
    int lane = threadIdx.x & 31;
    if (m >= M) return;
    float rv[8];
    float ss = 0.f;
#pragma unroll
    for (int i = 0; i < 8; i++) {
        rv[i] = raw[(size_t)m * DD + lane + 32 * i];
        ss += rv[i] * rv[i];
    }
    ss = warp_sum(ss);
    float rinv = 1.f / fmaxf(sqrtf(ss), 1e-8f);
    float sim[NC];
#pragma unroll
    for (int c = 0; c < NC; c++) {
        float s = 0.f;
#pragma unroll
        for (int i = 0; i < 8; i++) s += rv[i] * sAn[c * DD + lane + 32 * i];
        sim[c] = warp_sum(s) * rinv;
    }
    if (lane == 0) {
        float mx = sim[0];
#pragma unroll
        for (int c = 1; c < NC; c++) mx = fmaxf(mx, sim[c]);
        float e[NC], s = 0.f;
#pragma unroll
        for (int c = 0; c < NC; c++) { e[c] = expf(sim[c] - mx); s += e[c]; }
        float inv = 1.f / s;
#pragma unroll
        for (int c = 0; c < NC; c++) out[(size_t)m * NC + c] = e[c] * inv;
    }
}

// ---------------------------------------------------------------------------
// Orchestration
// ---------------------------------------------------------------------------
extern "C" void kernel_launch(void* const* d_in, const int* in_sizes, int n_in,
                              void* d_out, int out_size)
{
    const float* x0     = (const float*)d_in[0];
    const int*   src    = (const int*)d_in[1];
    const int*   dst    = (const int*)d_in[2];
    const int*   idx    = (const int*)d_in[3];
    const int*   labels = (const int*)d_in[4];
    const float* W1 = (const float*)d_in[6];
    const float* b1 = (const float*)d_in[7];
    const float* W2 = (const float*)d_in[8];
    const float* b2 = (const float*)d_in[9];
    const float* W3 = (const float*)d_in[10];
    const float* b3 = (const float*)d_in[11];
    const float* cw_in  = (const float*)d_in[12];
    const float* cb_in  = (const float*)d_in[13];
    const float* cw_hid = (const float*)d_in[14];
    const float* cb_hid = (const float*)d_in[15];
    const float* cw_out = (const float*)d_in[16];
    const float* cb_out = (const float*)d_in[17];
    const float* p_list = (const float*)d_in[18];
    const float* aW     = (const float*)d_in[19];
    const float* ab     = (const float*)d_in[20];
    const float* gw2    = (const float*)d_in[21];

    const int N = in_sizes[0] / DD;
    const int E = in_sizes[1];
    const int M = in_sizes[3];
    float* out = (float*)d_out;

    uint8_t *bx8, *bx08, *bh8, *be18, *be28;
    float *bdinv, *binvdeg, *braw, *bsums, *ban;
    uint32_t* bwq;
    int *bdegi, *browptr, *bcursor;
    int2* bepack;
    cudaGetSymbolAddress((void**)&bx8,  g_x8);
    cudaGetSymbolAddress((void**)&bx08, g_x08);
    cudaGetSymbolAddress((void**)&bh8,  g_h8);
    cudaGetSymbolAddress((void**)&be18, g_e18);
    cudaGetSymbolAddress((void**)&be28, g_e28);
    cudaGetSymbolAddress((void**)&bwq,  g_wq);
    cudaGetSymbolAddress((void**)&bdegi, g_degi);
    cudaGetSymbolAddress((void**)&bdinv, g_dinv);
    cudaGetSymbolAddress((void**)&binvdeg, g_invdeg);
    cudaGetSymbolAddress((void**)&browptr, g_rowptr);
    cudaGetSymbolAddress((void**)&bcursor, g_cursor);
    cudaGetSymbolAddress((void**)&bepack, g_epack);
    cudaGetSymbolAddress((void**)&braw, g_raw);
    cudaGetSymbolAddress((void**)&bsums, g_sums);
    cudaGetSymbolAddress((void**)&ban, g_an);
    float* bcnt = bsums + NC * DD;

    const bool fork = g_si.ok;
    cudaStream_t s2 = fork ? g_si.s2 : (cudaStream_t)0;

    // --- fork: CSR build + bsums clear on side stream ---
    if (fork) {
        cudaEventRecord(g_si.ev1, 0);
        cudaStreamWaitEvent(s2, g_si.ev1, 0);
    }
    cudaMemsetAsync(bdegi, 0, (size_t)N * sizeof(int), s2);
    cudaMemsetAsync(bsums, 0, (NC * DD + 32) * sizeof(float), s2);
    count_deg<<<(E + 255) / 256, 256, 0, s2>>>(dst, bdegi, E);
    finalize_deg<<<(N + 255) / 256, 256, 0, s2>>>(bdegi, bdinv, binvdeg, N);
    scan_rowptr<<<1, 1024, 0, s2>>>(bdegi, browptr, bcursor, N);
    fill_csr<<<(E + 255) / 256, 256, 0, s2>>>(src, dst, bdinv, bcursor, bepack, E);
    if (fork) cudaEventRecord(g_si.ev2, s2);

    // --- main stream: prepack + convert + GEMM chain ---
    prepack_weights_fp8<<<dim3(64, 12), 256>>>(W1, W2, W3, cw_in, cw_hid, cw_out, bwq);
    {
        int n8 = N * DD / 8;
        conv_f32_fp8<<<(n8 + 255) / 256, 256>>>(x0, bx08, n8);
    }

    const dim3 gg((N + 127) / 128, 2);
    const int rowBlocks = (N + 7) / 8;
    const uint32_t* wq1 = bwq;
    const uint32_t* wq2 = bwq + 1 * 16384;
    const uint32_t* wq3 = bwq + 2 * 16384;

    bool joined = false;
    const uint8_t* cur = bx08;
    for (int t = 0; t < 3; t++) {
        fp8_gemm<0><<<gg, 256>>>(cur, wq1, nullptr, nullptr, bh8, N);
        if (!joined) {
            if (fork) cudaStreamWaitEvent(0, g_si.ev2, 0);
            joined = true;
        }
        gather_gcn_fp8<0, 0, 0><<<rowBlocks, 256>>>(bh8, browptr, bepack, b1, binvdeg,
                                                    nullptr, nullptr, be18, N);
        fp8_gemm<0><<<gg, 256>>>(be18, wq2, nullptr, nullptr, bh8, N);
        gather_gcn_fp8<1, 1, 0><<<rowBlocks, 256>>>(bh8, browptr, bepack, b2, binvdeg,
                                                    be18, gw2, be28, N);
        fp8_gemm<1><<<gg, 256>>>(be28, bwq + (size_t)(3 + t) * 16384, cb_in + t * DD,
                                 nullptr, bh8, N);
        fp8_gemm<1><<<gg, 256>>>(bh8, bwq + (size_t)(6 + t) * 16384, cb_hid + t * DD,
                                 nullptr, be18, N);
        fp8_gemm<2><<<gg, 256>>>(be18, bwq + (size_t)(9 + t) * 16384, cb_out + t * DD,
                                 bx08, bx8, N);
        cur = bx8;
    }

    fp8_gemm<0><<<gg, 256>>>(bx8, wq1, nullptr, nullptr, bh8, N);
    gather_gcn_fp8<0, 0, 1><<<rowBlocks, 256>>>(bh8, browptr, bepack, b1, binvdeg,
                                                nullptr, nullptr, be18, N);
    fp8_gemm<0><<<gg, 256>>>(be18, wq2, nullptr, nullptr, bh8, N);
    gather_gcn_fp8<0, 0, 1><<<rowBlocks, 256>>>(bh8, browptr, bepack, b2, binvdeg,
                                                nullptr, nullptr, be28, N);
    fp8_gemm<0><<<gg, 256>>>(be28, wq3, nullptr, nullptr, bh8, N);
    gather_gcn_fp8<0, 0, 1><<<rowBlocks, 256>>>(bh8, browptr, bepack, b3, binvdeg,
                                                nullptr, nullptr, be18, N);

    embed_select<<<(M + 7) / 8, 256>>>(be18, aW, ab, p_list, idx, braw, M);

    proto_accum<<<(M + 7) / 8, 256>>>(braw, labels, M);
    an_finalize<<<NC, 32>>>(bsums, bcnt, ban);
    cos_softmax<<<(M + 7) / 8, 256>>>(braw, ban, out, M);
}

// round 15
// speedup vs baseline: 1.1185x; 1.1185x over previous
#include <cuda_runtime.h>
#include <cuda_bf16.h>
#include <cuda_fp16.h>
#include <math.h>
#include <stdint.h>

// ---------------------------------------------------------------------------
// downprompt. R15: revert R14 fp8-GEMM regression -> R13 config (bf16 HMMA
// GEMMs, fp8 HFMA2 gather w/ packed edges, side-stream CSR build).
// New: embed_select + proto_accum fused (one launch, raw stays in regs).
// ---------------------------------------------------------------------------

#define DD   256
#define MAXN 20000
#define MAXE 320000
#define MAXM 2048
#define NC   10

typedef __nv_bfloat16 bf16;
typedef __nv_bfloat162 bf162;

__device__ bf16    g_xb [MAXN * DD];
__device__ bf16    g_x0b[MAXN * DD];
__device__ bf16    g_hb [MAXN * DD];
__device__ uint8_t g_h8 [MAXN * DD];
__device__ bf16    g_e1b[MAXN * DD];
__device__ bf16    g_e2b[MAXN * DD];
__device__ uint32_t g_wp[12 * 32768];
__device__ int   g_degi[MAXN];
__device__ float g_dinv[MAXN];
__device__ float g_invdeg[MAXN];
__device__ int   g_rowptr[MAXN + 4];
__device__ int   g_cursor[MAXN + 4];
__device__ int2  g_epack[MAXE];
__device__ float g_raw[MAXM * DD];
__device__ float g_sums[NC * DD + 32];
__device__ float g_an[NC * DD];

struct StreamInit {
    cudaStream_t s2 = nullptr;
    cudaEvent_t ev1 = nullptr, ev2 = nullptr;
    bool ok = false;
    StreamInit() {
        ok = (cudaStreamCreateWithFlags(&s2, cudaStreamNonBlocking) == cudaSuccess) &&
             (cudaEventCreateWithFlags(&ev1, cudaEventDisableTiming) == cudaSuccess) &&
             (cudaEventCreateWithFlags(&ev2, cudaEventDisableTiming) == cudaSuccess);
    }
};
static StreamInit g_si;

__device__ __forceinline__ float warp_sum(float v) {
#pragma unroll
    for (int o = 16; o > 0; o >>= 1) v += __shfl_xor_sync(0xffffffffu, v, o);
    return v;
}

__device__ __forceinline__ void mma_bf16(
    float& c0, float& c1, float& c2, float& c3,
    uint32_t a0, uint32_t a1, uint32_t a2, uint32_t a3,
    uint32_t b0, uint32_t b1)
{
    asm volatile(
        "mma.sync.aligned.m16n8k16.row.col.f32.bf16.bf16.f32 "
        "{%0,%1,%2,%3},{%4,%5,%6,%7},{%8,%9},{%0,%1,%2,%3};"
        : "+f"(c0), "+f"(c1), "+f"(c2), "+f"(c3)
        : "r"(a0), "r"(a1), "r"(a2), "r"(a3), "r"(b0), "r"(b1));
}

__device__ __forceinline__ void cp_async16(void* smem_dst, const void* gmem_src, int src_bytes) {
    uint32_t s = (uint32_t)__cvta_generic_to_shared(smem_dst);
    asm volatile("cp.async.cg.shared.global [%0], [%1], 16, %2;"
                 :: "r"(s), "l"(gmem_src), "r"(src_bytes));
}

// ---------------------------------------------------------------------------
// Weight prepack (bf16 k-pair layout)
// ---------------------------------------------------------------------------
__global__ void __launch_bounds__(256) prepack_weights(
    const float* __restrict__ W1, const float* __restrict__ W2,
    const float* __restrict__ W3, const float* __restrict__ cw_in,
    const float* __restrict__ cw_hid, const float* __restrict__ cw_out,
    uint32_t* __restrict__ wp)
{
    int m = blockIdx.y;
    const float* W =
        (m == 0) ? W1 : (m == 1) ? W2 : (m == 2) ? W3 :
        (m < 6) ? cw_in  + (size_t)(m - 3) * 65536 :
        (m < 9) ? cw_hid + (size_t)(m - 6) * 65536 :
                  cw_out + (size_t)(m - 9) * 65536;
    int i = blockIdx.x * 256 + threadIdx.x;
    int k2 = i >> 8, n = i & 255;
    float lo = W[(size_t)(2 * k2) * 256 + n];
    float hi = W[(size_t)(2 * k2 + 1) * 256 + n];
    bf162 p = __floats2bfloat162_rn(lo, hi);
    wp[(size_t)m * 32768 + i] = *(uint32_t*)&p;
}

__global__ void __launch_bounds__(256) conv_f32_bf16(
    const float* __restrict__ in, bf16* __restrict__ out, int n4)
{
    int i = blockIdx.x * blockDim.x + threadIdx.x;
    if (i >= n4) return;
    float4 v = ((const float4*)in)[i];
    bf162 a = __floats2bfloat162_rn(v.x, v.y);
    bf162 b = __floats2bfloat162_rn(v.z, v.w);
    uint2 u;
    u.x = *(uint32_t*)&a;
    u.y = *(uint32_t*)&b;
    ((uint2*)out)[i] = u;
}

// ---------------------------------------------------------------------------
// bf16 GEMM: 128x128 tile, BK=32, 2-stage cp.async, 8 warps (4M x 2N).
// EPI 0: plain. EPI 1: elu(acc+bias). EPI 2: (acc+bias)*extra(bf16)
// OUT8: write e4m3 (gather input), else bf16.
// ---------------------------------------------------------------------------
#define ASB   40
#define BSPW  136

template <int EPI, int OUT8>
__global__ void __launch_bounds__(256) bf16_gemm(
    const bf16* __restrict__ A, const uint32_t* __restrict__ Wp,
    const float* __restrict__ bias, const bf16* __restrict__ extra,
    void* __restrict__ Cv, int N)
{
    __shared__ __align__(16) bf16     As[2][128 * ASB];
    __shared__ __align__(16) uint32_t Bsp[2][16 * BSPW];

    const int tid  = threadIdx.x;
    const int lane = tid & 31;
    const int wid  = tid >> 5;
    const int wm   = wid & 3;
    const int wn   = wid >> 2;
    const int rowBase = blockIdx.x * 128;
    const int colBase = blockIdx.y * 128;
    const int lq = lane >> 2;
    const int lr = lane & 3;

    float acc[2][8][4];
#pragma unroll
    for (int mt = 0; mt < 2; mt++)
#pragma unroll
        for (int nt = 0; nt < 8; nt++)
#pragma unroll
            for (int i = 0; i < 4; i++) acc[mt][nt][i] = 0.f;

    auto loadTile = [&](int k0, int st) {
#pragma unroll
        for (int i = 0; i < 2; i++) {
            int ch = tid + i * 256;
            int r  = ch >> 2;
            int kc = (ch & 3) * 8;
            int grow = rowBase + r;
            int ok = (grow < N) ? 16 : 0;
            int crow = (grow < N) ? grow : (N - 1);
            cp_async16(&As[st][r * ASB + kc], A + (size_t)crow * 256 + k0 + kc, ok);
        }
#pragma unroll
        for (int i = 0; i < 2; i++) {
            int ch = tid + i * 256;
            int k2 = ch >> 5;
            int nc = (ch & 31) * 4;
            cp_async16(&Bsp[st][k2 * BSPW + nc],
                       Wp + (size_t)(k0 / 2 + k2) * 256 + colBase + nc, 16);
        }
        asm volatile("cp.async.commit_group;");
    };

    loadTile(0, 0);
#pragma unroll
    for (int it = 0; it < 8; it++) {
        if (it < 7) {
            loadTile((it + 1) * 32, (it + 1) & 1);
            asm volatile("cp.async.wait_group 1;");
        } else {
            asm volatile("cp.async.wait_group 0;");
        }
        __syncthreads();
        const bf16* As_ = As[it & 1];
        const uint32_t* Bp = Bsp[it & 1];
#pragma unroll
        for (int ks = 0; ks < 2; ks++) {
            uint32_t a[2][4];
#pragma unroll
            for (int mt = 0; mt < 2; mt++) {
                int r = wm * 32 + mt * 16 + lq;
                const uint32_t* ar0 = (const uint32_t*)(As_ + r * ASB) + ks * 8 + lr;
                const uint32_t* ar1 = (const uint32_t*)(As_ + (r + 8) * ASB) + ks * 8 + lr;
                a[mt][0] = ar0[0];
                a[mt][1] = ar1[0];
                a[mt][2] = ar0[4];
                a[mt][3] = ar1[4];
            }
            uint32_t b0[8], b1[8];
#pragma unroll
            for (int nt = 0; nt < 8; nt++) {
                int n = wn * 64 + nt * 8 + lq;
                b0[nt] = Bp[(ks * 8 + lr) * BSPW + n];
                b1[nt] = Bp[(ks * 8 + lr + 4) * BSPW + n];
            }
#pragma unroll
            for (int mt = 0; mt < 2; mt++)
#pragma unroll
                for (int nt = 0; nt < 8; nt++)
                    mma_bf16(acc[mt][nt][0], acc[mt][nt][1], acc[mt][nt][2], acc[mt][nt][3],
                             a[mt][0], a[mt][1], a[mt][2], a[mt][3], b0[nt], b1[nt]);
        }
        __syncthreads();
    }

#pragma unroll
    for (int mt = 0; mt < 2; mt++) {
#pragma unroll
        for (int rr = 0; rr < 2; rr++) {
            int row = rowBase + wm * 32 + mt * 16 + lq + rr * 8;
            if (row >= N) continue;
#pragma unroll
            for (int nt = 0; nt < 8; nt++) {
                int col = colBase + wn * 64 + nt * 8 + 2 * lr;
                float v0 = acc[mt][nt][rr * 2 + 0];
                float v1 = acc[mt][nt][rr * 2 + 1];
                if (EPI >= 1) { v0 += bias[col]; v1 += bias[col + 1]; }
                if (EPI == 1) {
                    v0 = v0 > 0.f ? v0 : expm1f(v0);
                    v1 = v1 > 0.f ? v1 : expm1f(v1);
                }
                if (EPI == 2) {
                    float2 ex = __bfloat1622float2(
                        *(const bf162*)(extra + (size_t)row * 256 + col));
                    v0 *= ex.x; v1 *= ex.y;
                }
                if (OUT8) {
                    unsigned short p;
                    asm("cvt.rn.satfinite.e4m3x2.f32 %0, %1, %2;"
                        : "=h"(p) : "f"(v1), "f"(v0));
                    *(unsigned short*)((uint8_t*)Cv + (size_t)row * 256 + col) = p;
                } else {
                    *(bf162*)((bf16*)Cv + (size_t)row * 256 + col) =
                        __floats2bfloat162_rn(v0, v1);
                }
            }
        }
    }
}

// ---------------------------------------------------------------------------
// CSR build (side stream)
// ---------------------------------------------------------------------------
__global__ void count_deg(const int* __restrict__ dst, int* __restrict__ degi, int E) {
    int e = blockIdx.x * blockDim.x + threadIdx.x;
    if (e < E) atomicAdd(&degi[dst[e]], 1);
}

__global__ void finalize_deg(const int* __restrict__ degi, float* __restrict__ dinv,
                             float* __restrict__ invdeg, int N) {
    int i = blockIdx.x * blockDim.x + threadIdx.x;
    if (i < N) {
        float d = (float)degi[i] + 1.f;
        dinv[i] = rsqrtf(d);
        invdeg[i] = 1.f / d;
    }
}

__global__ void __launch_bounds__(1024) scan_rowptr(
    const int* __restrict__ degi, int* __restrict__ rowptr, int* __restrict__ cursor, int N)
{
    __shared__ int warpTot[32];
    const int t = threadIdx.x;
    const int lane = t & 31;
    const int warp = t >> 5;
    const int n4 = N >> 2;
    const int per4 = (n4 + 1023) >> 10;
    const int b4 = t * per4;
    const int e4 = min(b4 + per4, n4);
    const int cnt = max(e4 - b4, 0);

    int4 v[8];
    int sum = 0;
    for (int i = 0; i < cnt; i++) {
        v[i] = ((const int4*)degi)[b4 + i];
        sum += v[i].x + v[i].y + v[i].z + v[i].w;
    }

    int inc = sum;
#pragma unroll
    for (int off = 1; off < 32; off <<= 1) {
        int x = __shfl_up_sync(0xffffffffu, inc, off);
        if (lane >= off) inc += x;
    }
    if (lane == 31) warpTot[warp] = inc;
    __syncthreads();
    if (warp == 0) {
        int wv = warpTot[lane];
        int winc = wv;
#pragma unroll
        for (int off = 1; off < 32; off <<= 1) {
            int x = __shfl_up_sync(0xffffffffu, winc, off);
            if (lane >= off) winc += x;
        }
        warpTot[lane] = winc - wv;
    }
    __syncthreads();
    int run = warpTot[warp] + inc - sum;

    for (int i = 0; i < cnt; i++) {
        int base4 = b4 + i;
        int d0 = v[i].x, d1 = v[i].y, d2 = v[i].z, d3 = v[i].w;
        int r0 = run, r1 = r0 + d0, r2 = r1 + d1, r3 = r2 + d2;
        run = r3 + d3;
        int4 rp = make_int4(r0, r1, r2, r3);
        ((int4*)rowptr)[base4] = rp;
        ((int4*)cursor)[base4] = rp;
    }
    if (t == 1023) {
        int run2 = run;
        for (int i = n4 * 4; i < N; i++) {
            rowptr[i] = run2;
            cursor[i] = run2;
            run2 += degi[i];
        }
        rowptr[N] = run2;
    }
}

__global__ void fill_csr(const int* __restrict__ src, const int* __restrict__ dst,
                         const float* __restrict__ dinv, int* __restrict__ cursor,
                         int2* __restrict__ epack, int E)
{
    int e = blockIdx.x * blockDim.x + threadIdx.x;
    if (e >= E) return;
    int s = src[e], d = dst[e];
    int slot = atomicAdd(&cursor[d], 1);
    float cf = dinv[s] * dinv[d];
    __half2 c2 = __float2half2_rn(cf);
    epack[slot] = make_int2(s * DD, (int)*(uint32_t*)&c2);
}

// ---------------------------------------------------------------------------
// Gather SpMM (fp8 in, bf16 out), half2 HFMA2 accumulation, packed edges.
// ---------------------------------------------------------------------------
__device__ __forceinline__ void accum_h2(__half2* acc, uint2 v, __half2 c2) {
    uint32_t h0, h1, h2, h3;
    asm("cvt.rn.f16x2.e4m3x2 %0, %1;" : "=r"(h0) : "h"((unsigned short)(v.x & 0xffffu)));
    asm("cvt.rn.f16x2.e4m3x2 %0, %1;" : "=r"(h1) : "h"((unsigned short)(v.x >> 16)));
    asm("cvt.rn.f16x2.e4m3x2 %0, %1;" : "=r"(h2) : "h"((unsigned short)(v.y & 0xffffu)));
    asm("cvt.rn.f16x2.e4m3x2 %0, %1;" : "=r"(h3) : "h"((unsigned short)(v.y >> 16)));
    acc[0] = __hfma2(*(__half2*)&h0, c2, acc[0]);
    acc[1] = __hfma2(*(__half2*)&h1, c2, acc[1]);
    acc[2] = __hfma2(*(__half2*)&h2, c2, acc[2]);
    acc[3] = __hfma2(*(__half2*)&h3, c2, acc[3]);
}

__device__ __forceinline__ void accum8_bf16(float* acc, uint4 v, float c) {
    bf162* p = (bf162*)&v;
#pragma unroll
    for (int j = 0; j < 4; j++) {
        float2 f = __bfloat1622float2(p[j]);
        acc[2 * j]     += f.x * c;
        acc[2 * j + 1] += f.y * c;
    }
}

template <int RES, int SCALE, int ELU>
__global__ void __launch_bounds__(256) gather_gcn_fp8(
    const uint8_t* __restrict__ h, const int* __restrict__ rowptr,
    const int2* __restrict__ epack,
    const float* __restrict__ bias, const float* __restrict__ invdeg,
    const bf16* __restrict__ res, const float* __restrict__ scale_ptr,
    bf16* __restrict__ out, int N)
{
    int d = (blockIdx.x * blockDim.x + threadIdx.x) >> 5;
    int lane = threadIdx.x & 31;
    if (d >= N) return;

    const int eBeg = rowptr[d];
    const int eEnd = rowptr[d + 1];
    const int coff = lane * 8;
    const uint8_t* hbase = h + coff;

    __half2 hacc[4];
    __half2 hz = __float2half2_rn(0.f);
#pragma unroll
    for (int j = 0; j < 4; j++) hacc[j] = hz;

    int e = eBeg;
    for (; e + 7 < eEnd; e += 8) {
        int2  p[8];
        uint2 v[8];
#pragma unroll
        for (int j = 0; j < 8; j++) p[j] = epack[e + j];
#pragma unroll
        for (int j = 0; j < 8; j++) v[j] = *(const uint2*)(hbase + p[j].x);
#pragma unroll
        for (int j = 0; j < 8; j++) accum_h2(hacc, v[j], *(__half2*)&p[j].y);
    }
    for (; e + 1 < eEnd; e += 2) {
        int2 p0 = epack[e], p1 = epack[e + 1];
        uint2 v0 = *(const uint2*)(hbase + p0.x);
        uint2 v1 = *(const uint2*)(hbase + p1.x);
        accum_h2(hacc, v0, *(__half2*)&p0.y);
        accum_h2(hacc, v1, *(__half2*)&p1.y);
    }
    if (e < eEnd) {
        int2 p0 = epack[e];
        uint2 v0 = *(const uint2*)(hbase + p0.x);
        accum_h2(hacc, v0, *(__half2*)&p0.y);
    }

    uint2 vs = *(const uint2*)(hbase + d * DD);
    accum_h2(hacc, vs, __float2half2_rn(invdeg[d]));

    float acc[8];
#pragma unroll
    for (int j = 0; j < 4; j++) {
        float2 f = __half22float2(hacc[j]);
        acc[2 * j] = f.x;
        acc[2 * j + 1] = f.y;
    }
    float4 b0 = ((const float4*)bias)[lane * 2];
    float4 b1 = ((const float4*)bias)[lane * 2 + 1];
    acc[0] += b0.x; acc[1] += b0.y; acc[2] += b0.z; acc[3] += b0.w;
    acc[4] += b1.x; acc[5] += b1.y; acc[6] += b1.z; acc[7] += b1.w;

    if (RES) {
        uint4 rv = *(const uint4*)(res + (size_t)d * DD + coff);
        accum8_bf16(acc, rv, 1.f);
    }
    if (SCALE) {
        float sc = scale_ptr[0];
#pragma unroll
        for (int j = 0; j < 8; j++) acc[j] *= sc;
    }
    if (ELU) {
#pragma unroll
        for (int j = 0; j < 8; j++) acc[j] = acc[j] > 0.f ? acc[j] : expm1f(acc[j]);
    }
    uint4 ov;
    bf162* op = (bf162*)&ov;
#pragma unroll
    for (int j = 0; j < 4; j++) op[j] = __floats2bfloat162_rn(acc[2 * j], acc[2 * j + 1]);
    *(uint4*)(out + (size_t)d * DD + coff) = ov;
}

// ---------------------------------------------------------------------------
// Fused: prompt attention on M rows + prototype accumulation. 1 warp / row.
// raw[m] written once; prototype sums accumulated directly from registers.
// ---------------------------------------------------------------------------
__global__ void __launch_bounds__(256) embed_proto(
    const bf16* __restrict__ h, const float* __restrict__ aW,
    const float* __restrict__ ab, const float* __restrict__ p,
    const int* __restrict__ idx, const int* __restrict__ labels,
    float* __restrict__ raw, int M)
{
    int m = (blockIdx.x * blockDim.x + threadIdx.x) >> 5;
    int lane = threadIdx.x & 31;
    if (m >= M) return;
    int node = idx[m];
    const bf16* hr = h + (size_t)node * DD;
    float hv[8];
    float lg[5] = {0.f, 0.f, 0.f, 0.f, 0.f};
#pragma unroll
    for (int i = 0; i < 8; i++) {
        int c = lane + 32 * i;
        hv[i] = __bfloat162float(hr[c]);
#pragma unroll
        for (int k = 0; k < 5; k++) lg[k] += hv[i] * aW[c * 5 + k];
    }
#pragma unroll
    for (int k = 0; k < 5; k++) lg[k] = warp_sum(lg[k]) + ab[k];
    float mx = lg[0];
#pragma unroll
    for (int k = 1; k < 5; k++) mx = fmaxf(mx, lg[k]);
    float wgt[5], s = 0.f;
#pragma unroll
    for (int k = 0; k < 5; k++) { wgt[k] = expf(lg[k] - mx); s += wgt[k]; }
    float inv = 1.f / s;
#pragma unroll
    for (int k = 0; k < 5; k++) wgt[k] *= inv;

    int lab = labels[m];
#pragma unroll
    for (int i = 0; i < 8; i++) {
        int c = lane + 32 * i;
        float v = hv[i];
#pragma unroll
        for (int k = 0; k < 5; k++) v += wgt[k] * p[k * DD + c];
        raw[(size_t)m * DD + c] = v;
        atomicAdd(&g_sums[lab * DD + c], v);
    }
    if (lane == 0) atomicAdd(&g_sums[NC * DD + lab], 1.f);
}

__global__ void an_finalize(const float* __restrict__ sums,
                            const float* __restrict__ cnt, float* __restrict__ an)
{
    int c = blockIdx.x;
    int lane = threadIdx.x;
    float invc = 1.f / fmaxf(cnt[c], 1.f);
    float v[8];
    float ss = 0.f;
#pragma unroll
    for (int i = 0; i < 8; i++) {
        v[i] = sums[c * DD + lane + 32 * i] * invc;
        ss += v[i] * v[i];
    }
    ss = warp_sum(ss);
    float innorm = 1.f / fmaxf(sqrtf(ss), 1e-8f);
#pragma unroll
    for (int i = 0; i < 8; i++) an[c * DD + lane + 32 * i] = v[i] * innorm;
}

__global__ void __launch_bounds__(256) cos_softmax(
    const float* __restrict__ raw, const float* __restrict__ an,
    float* __restrict__ out, int M)
{
    __shared__ float sAn[NC * DD];
    for (int i = threadIdx.x; i < NC * DD; i += 256) sAn[i] = an[i];
    __syncthreads();
    int m = (blockIdx.x * blockDim.x + threadIdx.x) >> 5;
    int lane = threadIdx.x & 31;
    if (m >= M) return;
    float rv[8];
    float ss = 0.f;
#pragma unroll
    for (int i = 0; i < 8; i++) {
        rv[i] = raw[(size_t)m * DD + lane + 32 * i];
        ss += rv[i] * rv[i];
    }
    ss = warp_sum(ss);
    float rinv = 1.f / fmaxf(sqrtf(ss), 1e-8f);
    float sim[NC];
#pragma unroll
    for (int c = 0; c < NC; c++) {
        float s = 0.f;
#pragma unroll
        for (int i = 0; i < 8; i++) s += rv[i] * sAn[c * DD + lane + 32 * i];
        sim[c] = warp_sum(s) * rinv;
    }
    if (lane == 0) {
        float mx = sim[0];
#pragma unroll
        for (int c = 1; c < NC; c++) mx = fmaxf(mx, sim[c]);
        float e[NC], s = 0.f;
#pragma unroll
        for (int c = 0; c < NC; c++) { e[c] = expf(sim[c] - mx); s += e[c]; }
        float inv = 1.f / s;
#pragma unroll
        for (int c = 0; c < NC; c++) out[(size_t)m * NC + c] = e[c] * inv;
    }
}

// ---------------------------------------------------------------------------
// Orchestration
// ---------------------------------------------------------------------------
extern "C" void kernel_launch(void* const* d_in, const int* in_sizes, int n_in,
                              void* d_out, int out_size)
{
    const float* x0     = (const float*)d_in[0];
    const int*   src    = (const int*)d_in[1];
    const int*   dst    = (const int*)d_in[2];
    const int*   idx    = (const int*)d_in[3];
    const int*   labels = (const int*)d_in[4];
    const float* W1 = (const float*)d_in[6];
    const float* b1 = (const float*)d_in[7];
    const float* W2 = (const float*)d_in[8];
    const float* b2 = (const float*)d_in[9];
    const float* W3 = (const float*)d_in[10];
    const float* b3 = (const float*)d_in[11];
    const float* cw_in  = (const float*)d_in[12];
    const float* cb_in  = (const float*)d_in[13];
    const float* cw_hid = (const float*)d_in[14];
    const float* cb_hid = (const float*)d_in[15];
    const float* cw_out = (const float*)d_in[16];
    const float* cb_out = (const float*)d_in[17];
    const float* p_list = (const float*)d_in[18];
    const float* aW     = (const float*)d_in[19];
    const float* ab     = (const float*)d_in[20];
    const float* gw2    = (const float*)d_in[21];

    const int N = in_sizes[0] / DD;
    const int E = in_sizes[1];
    const int M = in_sizes[3];
    float* out = (float*)d_out;

    bf16 *bxb, *bx0b, *bhb, *be1b, *be2b;
    uint8_t* bh8;
    float *bdinv, *binvdeg, *braw, *bsums, *ban;
    uint32_t* bwp;
    int *bdegi, *browptr, *bcursor;
    int2* bepack;
    cudaGetSymbolAddress((void**)&bxb,  g_xb);
    cudaGetSymbolAddress((void**)&bx0b, g_x0b);
    cudaGetSymbolAddress((void**)&bhb,  g_hb);
    cudaGetSymbolAddress((void**)&bh8,  g_h8);
    cudaGetSymbolAddress((void**)&be1b, g_e1b);
    cudaGetSymbolAddress((void**)&be2b, g_e2b);
    cudaGetSymbolAddress((void**)&bwp,  g_wp);
    cudaGetSymbolAddress((void**)&bdegi, g_degi);
    cudaGetSymbolAddress((void**)&bdinv, g_dinv);
    cudaGetSymbolAddress((void**)&binvdeg, g_invdeg);
    cudaGetSymbolAddress((void**)&browptr, g_rowptr);
    cudaGetSymbolAddress((void**)&bcursor, g_cursor);
    cudaGetSymbolAddress((void**)&bepack, g_epack);
    cudaGetSymbolAddress((void**)&braw, g_raw);
    cudaGetSymbolAddress((void**)&bsums, g_sums);
    cudaGetSymbolAddress((void**)&ban, g_an);
    float* bcnt = bsums + NC * DD;

    const bool fork = g_si.ok;
    cudaStream_t s2 = fork ? g_si.s2 : (cudaStream_t)0;

    // --- fork: CSR build + bsums clear on side stream ---
    if (fork) {
        cudaEventRecord(g_si.ev1, 0);
        cudaStreamWaitEvent(s2, g_si.ev1, 0);
    }
    cudaMemsetAsync(bdegi, 0, (size_t)N * sizeof(int), s2);
    cudaMemsetAsync(bsums, 0, (NC * DD + 32) * sizeof(float), s2);
    count_deg<<<(E + 255) / 256, 256, 0, s2>>>(dst, bdegi, E);
    finalize_deg<<<(N + 255) / 256, 256, 0, s2>>>(bdegi, bdinv, binvdeg, N);
    scan_rowptr<<<1, 1024, 0, s2>>>(bdegi, browptr, bcursor, N);
    fill_csr<<<(E + 255) / 256, 256, 0, s2>>>(src, dst, bdinv, bcursor, bepack, E);
    if (fork) cudaEventRecord(g_si.ev2, s2);

    // --- main stream: prepack + convert + GEMM chain ---
    prepack_weights<<<dim3(128, 12), 256>>>(W1, W2, W3, cw_in, cw_hid, cw_out, bwp);
    {
        int n4 = N * DD / 4;
        conv_f32_bf16<<<(n4 + 255) / 256, 256>>>(x0, bx0b, n4);
    }

    const dim3 gg((N + 127) / 128, 2);
    const int rowBlocks = (N + 7) / 8;
    const uint32_t* wp1 = bwp;
    const uint32_t* wp2 = bwp + 1 * 32768;
    const uint32_t* wp3 = bwp + 2 * 32768;

    bool joined = false;
    const bf16* cur = bx0b;
    for (int t = 0; t < 3; t++) {
        bf16_gemm<0, 1><<<gg, 256>>>(cur, wp1, nullptr, nullptr, bh8, N);
        if (!joined) {
            if (fork) cudaStreamWaitEvent(0, g_si.ev2, 0);
            joined = true;
        }
        gather_gcn_fp8<0, 0, 0><<<rowBlocks, 256>>>(bh8, browptr, bepack, b1, binvdeg,
                                                    nullptr, nullptr, be1b, N);
        bf16_gemm<0, 1><<<gg, 256>>>(be1b, wp2, nullptr, nullptr, bh8, N);
        gather_gcn_fp8<1, 1, 0><<<rowBlocks, 256>>>(bh8, browptr, bepack, b2, binvdeg,
                                                    be1b, gw2, be2b, N);
        bf16_gemm<1, 0><<<gg, 256>>>(be2b, bwp + (size_t)(3 + t) * 32768, cb_in + t * DD,
                                     nullptr, bhb, N);
        bf16_gemm<1, 0><<<gg, 256>>>(bhb, bwp + (size_t)(6 + t) * 32768, cb_hid + t * DD,
                                     nullptr, be1b, N);
        bf16_gemm<2, 0><<<gg, 256>>>(be1b, bwp + (size_t)(9 + t) * 32768, cb_out + t * DD,
                                     bx0b, bxb, N);
        cur = bxb;
    }

    bf16_gemm<0, 1><<<gg, 256>>>(bxb, wp1, nullptr, nullptr, bh8, N);
    gather_gcn_fp8<0, 0, 1><<<rowBlocks, 256>>>(bh8, browptr, bepack, b1, binvdeg,
                                                nullptr, nullptr, be1b, N);
    bf16_gemm<0, 1><<<gg, 256>>>(be1b, wp2, nullptr, nullptr, bh8, N);
    gather_gcn_fp8<0, 0, 1><<<rowBlocks, 256>>>(bh8, browptr, bepack, b2, binvdeg,
                                                nullptr, nullptr, be2b, N);
    bf16_gemm<0, 1><<<gg, 256>>>(be2b, wp3, nullptr, nullptr, bh8, N);
    gather_gcn_fp8<0, 0, 1><<<rowBlocks, 256>>>(bh8, browptr, bepack, b3, binvdeg,
                                                nullptr, nullptr, be1b, N);

    embed_proto<<<(M + 7) / 8, 256>>>(be1b, aW, ab, p_list, idx, labels, braw, M);
    an_finalize<<<NC, 32>>>(bsums, bcnt, ban);
    cos_softmax<<<(M + 7) / 8, 256>>>(braw, ban, out, M);
}

// round 16
// speedup vs baseline: 1.1238x; 1.0047x over previous
#include <cuda_runtime.h>
#include <cuda_bf16.h>
#include <cuda_fp16.h>
#include <math.h>
#include <stdint.h>

// ---------------------------------------------------------------------------
// downprompt. R16: final GCN gather computed ONLY at the M=2048 idx rows,
// fused with prompt attention + prototype accumulation (one kernel).
// Rest = R15: bf16 HMMA GEMMs, fp8 HFMA2 gather w/ packed edges,
// side-stream CSR build, dead-e3 eliminated.
// ---------------------------------------------------------------------------

#define DD   256
#define MAXN 20000
#define MAXE 320000
#define MAXM 2048
#define NC   10

typedef __nv_bfloat16 bf16;
typedef __nv_bfloat162 bf162;

__device__ bf16    g_xb [MAXN * DD];
__device__ bf16    g_x0b[MAXN * DD];
__device__ bf16    g_hb [MAXN * DD];
__device__ uint8_t g_h8 [MAXN * DD];
__device__ bf16    g_e1b[MAXN * DD];
__device__ bf16    g_e2b[MAXN * DD];
__device__ uint32_t g_wp[12 * 32768];
__device__ int   g_degi[MAXN];
__device__ float g_dinv[MAXN];
__device__ float g_invdeg[MAXN];
__device__ int   g_rowptr[MAXN + 4];
__device__ int   g_cursor[MAXN + 4];
__device__ int2  g_epack[MAXE];
__device__ float g_raw[MAXM * DD];
__device__ float g_sums[NC * DD + 32];
__device__ float g_an[NC * DD];

struct StreamInit {
    cudaStream_t s2 = nullptr;
    cudaEvent_t ev1 = nullptr, ev2 = nullptr;
    bool ok = false;
    StreamInit() {
        ok = (cudaStreamCreateWithFlags(&s2, cudaStreamNonBlocking) == cudaSuccess) &&
             (cudaEventCreateWithFlags(&ev1, cudaEventDisableTiming) == cudaSuccess) &&
             (cudaEventCreateWithFlags(&ev2, cudaEventDisableTiming) == cudaSuccess);
    }
};
static StreamInit g_si;

__device__ __forceinline__ float warp_sum(float v) {
#pragma unroll
    for (int o = 16; o > 0; o >>= 1) v += __shfl_xor_sync(0xffffffffu, v, o);
    return v;
}

__device__ __forceinline__ void mma_bf16(
    float& c0, float& c1, float& c2, float& c3,
    uint32_t a0, uint32_t a1, uint32_t a2, uint32_t a3,
    uint32_t b0, uint32_t b1)
{
    asm volatile(
        "mma.sync.aligned.m16n8k16.row.col.f32.bf16.bf16.f32 "
        "{%0,%1,%2,%3},{%4,%5,%6,%7},{%8,%9},{%0,%1,%2,%3};"
        : "+f"(c0), "+f"(c1), "+f"(c2), "+f"(c3)
        : "r"(a0), "r"(a1), "r"(a2), "r"(a3), "r"(b0), "r"(b1));
}

__device__ __forceinline__ void cp_async16(void* smem_dst, const void* gmem_src, int src_bytes) {
    uint32_t s = (uint32_t)__cvta_generic_to_shared(smem_dst);
    asm volatile("cp.async.cg.shared.global [%0], [%1], 16, %2;"
                 :: "r"(s), "l"(gmem_src), "r"(src_bytes));
}

// ---------------------------------------------------------------------------
// Weight prepack (bf16 k-pair layout)
// ---------------------------------------------------------------------------
__global__ void __launch_bounds__(256) prepack_weights(
    const float* __restrict__ W1, const float* __restrict__ W2,
    const float* __restrict__ W3, const float* __restrict__ cw_in,
    const float* __restrict__ cw_hid, const float* __restrict__ cw_out,
    uint32_t* __restrict__ wp)
{
    int m = blockIdx.y;
    const float* W =
        (m == 0) ? W1 : (m == 1) ? W2 : (m == 2) ? W3 :
        (m < 6) ? cw_in  + (size_t)(m - 3) * 65536 :
        (m < 9) ? cw_hid + (size_t)(m - 6) * 65536 :
                  cw_out + (size_t)(m - 9) * 65536;
    int i = blockIdx.x * 256 + threadIdx.x;
    int k2 = i >> 8, n = i & 255;
    float lo = W[(size_t)(2 * k2) * 256 + n];
    float hi = W[(size_t)(2 * k2 + 1) * 256 + n];
    bf162 p = __floats2bfloat162_rn(lo, hi);
    wp[(size_t)m * 32768 + i] = *(uint32_t*)&p;
}

__global__ void __launch_bounds__(256) conv_f32_bf16(
    const float* __restrict__ in, bf16* __restrict__ out, int n4)
{
    int i = blockIdx.x * blockDim.x + threadIdx.x;
    if (i >= n4) return;
    float4 v = ((const float4*)in)[i];
    bf162 a = __floats2bfloat162_rn(v.x, v.y);
    bf162 b = __floats2bfloat162_rn(v.z, v.w);
    uint2 u;
    u.x = *(uint32_t*)&a;
    u.y = *(uint32_t*)&b;
    ((uint2*)out)[i] = u;
}

// ---------------------------------------------------------------------------
// bf16 GEMM: 128x128 tile, BK=32, 2-stage cp.async, 8 warps (4M x 2N).
// EPI 0: plain. EPI 1: elu(acc+bias). EPI 2: (acc+bias)*extra(bf16)
// OUT8: write e4m3 (gather input), else bf16.
// ---------------------------------------------------------------------------
#define ASB   40
#define BSPW  136

template <int EPI, int OUT8>
__global__ void __launch_bounds__(256) bf16_gemm(
    const bf16* __restrict__ A, const uint32_t* __restrict__ Wp,
    const float* __restrict__ bias, const bf16* __restrict__ extra,
    void* __restrict__ Cv, int N)
{
    __shared__ __align__(16) bf16     As[2][128 * ASB];
    __shared__ __align__(16) uint32_t Bsp[2][16 * BSPW];

    const int tid  = threadIdx.x;
    const int lane = tid & 31;
    const int wid  = tid >> 5;
    const int wm   = wid & 3;
    const int wn   = wid >> 2;
    const int rowBase = blockIdx.x * 128;
    const int colBase = blockIdx.y * 128;
    const int lq = lane >> 2;
    const int lr = lane & 3;

    float acc[2][8][4];
#pragma unroll
    for (int mt = 0; mt < 2; mt++)
#pragma unroll
        for (int nt = 0; nt < 8; nt++)
#pragma unroll
            for (int i = 0; i < 4; i++) acc[mt][nt][i] = 0.f;

    auto loadTile = [&](int k0, int st) {
#pragma unroll
        for (int i = 0; i < 2; i++) {
            int ch = tid + i * 256;
            int r  = ch >> 2;
            int kc = (ch & 3) * 8;
            int grow = rowBase + r;
            int ok = (grow < N) ? 16 : 0;
            int crow = (grow < N) ? grow : (N - 1);
            cp_async16(&As[st][r * ASB + kc], A + (size_t)crow * 256 + k0 + kc, ok);
        }
#pragma unroll
        for (int i = 0; i < 2; i++) {
            int ch = tid + i * 256;
            int k2 = ch >> 5;
            int nc = (ch & 31) * 4;
            cp_async16(&Bsp[st][k2 * BSPW + nc],
                       Wp + (size_t)(k0 / 2 + k2) * 256 + colBase + nc, 16);
        }
        asm volatile("cp.async.commit_group;");
    };

    loadTile(0, 0);
#pragma unroll
    for (int it = 0; it < 8; it++) {
        if (it < 7) {
            loadTile((it + 1) * 32, (it + 1) & 1);
            asm volatile("cp.async.wait_group 1;");
        } else {
            asm volatile("cp.async.wait_group 0;");
        }
        __syncthreads();
        const bf16* As_ = As[it & 1];
        const uint32_t* Bp = Bsp[it & 1];
#pragma unroll
        for (int ks = 0; ks < 2; ks++) {
            uint32_t a[2][4];
#pragma unroll
            for (int mt = 0; mt < 2; mt++) {
                int r = wm * 32 + mt * 16 + lq;
                const uint32_t* ar0 = (const uint32_t*)(As_ + r * ASB) + ks * 8 + lr;
                const uint32_t* ar1 = (const uint32_t*)(As_ + (r + 8) * ASB) + ks * 8 + lr;
                a[mt][0] = ar0[0];
                a[mt][1] = ar1[0];
                a[mt][2] = ar0[4];
                a[mt][3] = ar1[4];
            }
            uint32_t b0[8], b1[8];
#pragma unroll
            for (int nt = 0; nt < 8; nt++) {
                int n = wn * 64 + nt * 8 + lq;
                b0[nt] = Bp[(ks * 8 + lr) * BSPW + n];
                b1[nt] = Bp[(ks * 8 + lr + 4) * BSPW + n];
            }
#pragma unroll
            for (int mt = 0; mt < 2; mt++)
#pragma unroll
                for (int nt = 0; nt < 8; nt++)
                    mma_bf16(acc[mt][nt][0], acc[mt][nt][1], acc[mt][nt][2], acc[mt][nt][3],
                             a[mt][0], a[mt][1], a[mt][2], a[mt][3], b0[nt], b1[nt]);
        }
        __syncthreads();
    }

#pragma unroll
    for (int mt = 0; mt < 2; mt++) {
#pragma unroll
        for (int rr = 0; rr < 2; rr++) {
            int row = rowBase + wm * 32 + mt * 16 + lq + rr * 8;
            if (row >= N) continue;
#pragma unroll
            for (int nt = 0; nt < 8; nt++) {
                int col = colBase + wn * 64 + nt * 8 + 2 * lr;
                float v0 = acc[mt][nt][rr * 2 + 0];
                float v1 = acc[mt][nt][rr * 2 + 1];
                if (EPI >= 1) { v0 += bias[col]; v1 += bias[col + 1]; }
                if (EPI == 1) {
                    v0 = v0 > 0.f ? v0 : expm1f(v0);
                    v1 = v1 > 0.f ? v1 : expm1f(v1);
                }
                if (EPI == 2) {
                    float2 ex = __bfloat1622float2(
                        *(const bf162*)(extra + (size_t)row * 256 + col));
                    v0 *= ex.x; v1 *= ex.y;
                }
                if (OUT8) {
                    unsigned short p;
                    asm("cvt.rn.satfinite.e4m3x2.f32 %0, %1, %2;"
                        : "=h"(p) : "f"(v1), "f"(v0));
                    *(unsigned short*)((uint8_t*)Cv + (size_t)row * 256 + col) = p;
                } else {
                    *(bf162*)((bf16*)Cv + (size_t)row * 256 + col) =
                        __floats2bfloat162_rn(v0, v1);
                }
            }
        }
    }
}

// ---------------------------------------------------------------------------
// CSR build (side stream)
// ---------------------------------------------------------------------------
__global__ void count_deg(const int* __restrict__ dst, int* __restrict__ degi, int E) {
    int e = blockIdx.x * blockDim.x + threadIdx.x;
    if (e < E) atomicAdd(&degi[dst[e]], 1);
}

__global__ void finalize_deg(const int* __restrict__ degi, float* __restrict__ dinv,
                             float* __restrict__ invdeg, int N) {
    int i = blockIdx.x * blockDim.x + threadIdx.x;
    if (i < N) {
        float d = (float)degi[i] + 1.f;
        dinv[i] = rsqrtf(d);
        invdeg[i] = 1.f / d;
    }
}

__global__ void __launch_bounds__(1024) scan_rowptr(
    const int* __restrict__ degi, int* __restrict__ rowptr, int* __restrict__ cursor, int N)
{
    __shared__ int warpTot[32];
    const int t = threadIdx.x;
    const int lane = t & 31;
    const int warp = t >> 5;
    const int n4 = N >> 2;
    const int per4 = (n4 + 1023) >> 10;
    const int b4 = t * per4;
    const int e4 = min(b4 + per4, n4);
    const int cnt = max(e4 - b4, 0);

    int4 v[8];
    int sum = 0;
    for (int i = 0; i < cnt; i++) {
        v[i] = ((const int4*)degi)[b4 + i];
        sum += v[i].x + v[i].y + v[i].z + v[i].w;
    }

    int inc = sum;
#pragma unroll
    for (int off = 1; off < 32; off <<= 1) {
        int x = __shfl_up_sync(0xffffffffu, inc, off);
        if (lane >= off) inc += x;
    }
    if (lane == 31) warpTot[warp] = inc;
    __syncthreads();
    if (warp == 0) {
        int wv = warpTot[lane];
        int winc = wv;
#pragma unroll
        for (int off = 1; off < 32; off <<= 1) {
            int x = __shfl_up_sync(0xffffffffu, winc, off);
            if (lane >= off) winc += x;
        }
        warpTot[lane] = winc - wv;
    }
    __syncthreads();
    int run = warpTot[warp] + inc - sum;

    for (int i = 0; i < cnt; i++) {
        int base4 = b4 + i;
        int d0 = v[i].x, d1 = v[i].y, d2 = v[i].z, d3 = v[i].w;
        int r0 = run, r1 = r0 + d0, r2 = r1 + d1, r3 = r2 + d2;
        run = r3 + d3;
        int4 rp = make_int4(r0, r1, r2, r3);
        ((int4*)rowptr)[base4] = rp;
        ((int4*)cursor)[base4] = rp;
    }
    if (t == 1023) {
        int run2 = run;
        for (int i = n4 * 4; i < N; i++) {
            rowptr[i] = run2;
            cursor[i] = run2;
            run2 += degi[i];
        }
        rowptr[N] = run2;
    }
}

__global__ void fill_csr(const int* __restrict__ src, const int* __restrict__ dst,
                         const float* __restrict__ dinv, int* __restrict__ cursor,
                         int2* __restrict__ epack, int E)
{
    int e = blockIdx.x * blockDim.x + threadIdx.x;
    if (e >= E) return;
    int s = src[e], d = dst[e];
    int slot = atomicAdd(&cursor[d], 1);
    float cf = dinv[s] * dinv[d];
    __half2 c2 = __float2half2_rn(cf);
    epack[slot] = make_int2(s * DD, (int)*(uint32_t*)&c2);
}

// ---------------------------------------------------------------------------
// Gather SpMM (fp8 in, bf16 out), half2 HFMA2 accumulation, packed edges.
// ---------------------------------------------------------------------------
__device__ __forceinline__ void accum_h2(__half2* acc, uint2 v, __half2 c2) {
    uint32_t h0, h1, h2, h3;
    asm("cvt.rn.f16x2.e4m3x2 %0, %1;" : "=r"(h0) : "h"((unsigned short)(v.x & 0xffffu)));
    asm("cvt.rn.f16x2.e4m3x2 %0, %1;" : "=r"(h1) : "h"((unsigned short)(v.x >> 16)));
    asm("cvt.rn.f16x2.e4m3x2 %0, %1;" : "=r"(h2) : "h"((unsigned short)(v.y & 0xffffu)));
    asm("cvt.rn.f16x2.e4m3x2 %0, %1;" : "=r"(h3) : "h"((unsigned short)(v.y >> 16)));
    acc[0] = __hfma2(*(__half2*)&h0, c2, acc[0]);
    acc[1] = __hfma2(*(__half2*)&h1, c2, acc[1]);
    acc[2] = __hfma2(*(__half2*)&h2, c2, acc[2]);
    acc[3] = __hfma2(*(__half2*)&h3, c2, acc[3]);
}

__device__ __forceinline__ void accum8_bf16(float* acc, uint4 v, float c) {
    bf162* p = (bf162*)&v;
#pragma unroll
    for (int j = 0; j < 4; j++) {
        float2 f = __bfloat1622float2(p[j]);
        acc[2 * j]     += f.x * c;
        acc[2 * j + 1] += f.y * c;
    }
}

// Core: accumulate one row's GCN aggregation in half2, return fp32 acc[8].
__device__ __forceinline__ void gather_row_core(
    const uint8_t* __restrict__ hbase, const int* __restrict__ rowptr,
    const int2* __restrict__ epack, const float* __restrict__ invdeg,
    const float* __restrict__ bias, int d, int lane, float* acc)
{
    const int eBeg = rowptr[d];
    const int eEnd = rowptr[d + 1];

    __half2 hacc[4];
    __half2 hz = __float2half2_rn(0.f);
#pragma unroll
    for (int j = 0; j < 4; j++) hacc[j] = hz;

    int e = eBeg;
    for (; e + 7 < eEnd; e += 8) {
        int2  p[8];
        uint2 v[8];
#pragma unroll
        for (int j = 0; j < 8; j++) p[j] = epack[e + j];
#pragma unroll
        for (int j = 0; j < 8; j++) v[j] = *(const uint2*)(hbase + p[j].x);
#pragma unroll
        for (int j = 0; j < 8; j++) accum_h2(hacc, v[j], *(__half2*)&p[j].y);
    }
    for (; e + 1 < eEnd; e += 2) {
        int2 p0 = epack[e], p1 = epack[e + 1];
        uint2 v0 = *(const uint2*)(hbase + p0.x);
        uint2 v1 = *(const uint2*)(hbase + p1.x);
        accum_h2(hacc, v0, *(__half2*)&p0.y);
        accum_h2(hacc, v1, *(__half2*)&p1.y);
    }
    if (e < eEnd) {
        int2 p0 = epack[e];
        uint2 v0 = *(const uint2*)(hbase + p0.x);
        accum_h2(hacc, v0, *(__half2*)&p0.y);
    }

    uint2 vs = *(const uint2*)(hbase + d * DD);
    accum_h2(hacc, vs, __float2half2_rn(invdeg[d]));

#pragma unroll
    for (int j = 0; j < 4; j++) {
        float2 f = __half22float2(hacc[j]);
        acc[2 * j] = f.x;
        acc[2 * j + 1] = f.y;
    }
    float4 b0 = ((const float4*)bias)[lane * 2];
    float4 b1 = ((const float4*)bias)[lane * 2 + 1];
    acc[0] += b0.x; acc[1] += b0.y; acc[2] += b0.z; acc[3] += b0.w;
    acc[4] += b1.x; acc[5] += b1.y; acc[6] += b1.z; acc[7] += b1.w;
}

template <int RES, int SCALE, int ELU>
__global__ void __launch_bounds__(256) gather_gcn_fp8(
    const uint8_t* __restrict__ h, const int* __restrict__ rowptr,
    const int2* __restrict__ epack,
    const float* __restrict__ bias, const float* __restrict__ invdeg,
    const bf16* __restrict__ res, const float* __restrict__ scale_ptr,
    bf16* __restrict__ out, int N)
{
    int d = (blockIdx.x * blockDim.x + threadIdx.x) >> 5;
    int lane = threadIdx.x & 31;
    if (d >= N) return;
    const int coff = lane * 8;

    float acc[8];
    gather_row_core(h + coff, rowptr, epack, invdeg, bias, d, lane, acc);

    if (RES) {
        uint4 rv = *(const uint4*)(res + (size_t)d * DD + coff);
        accum8_bf16(acc, rv, 1.f);
    }
    if (SCALE) {
        float sc = scale_ptr[0];
#pragma unroll
        for (int j = 0; j < 8; j++) acc[j] *= sc;
    }
    if (ELU) {
#pragma unroll
        for (int j = 0; j < 8; j++) acc[j] = acc[j] > 0.f ? acc[j] : expm1f(acc[j]);
    }
    uint4 ov;
    bf162* op = (bf162*)&ov;
#pragma unroll
    for (int j = 0; j < 4; j++) op[j] = __floats2bfloat162_rn(acc[2 * j], acc[2 * j + 1]);
    *(uint4*)(out + (size_t)d * DD + coff) = ov;
}

// ---------------------------------------------------------------------------
// Fused FINAL layer: gather gcn3 at idx rows only + ELU + prompt attention +
// raw write + prototype accumulation. 1 warp per selected row.
// ---------------------------------------------------------------------------
__global__ void __launch_bounds__(256) gather_embed_proto(
    const uint8_t* __restrict__ h, const int* __restrict__ rowptr,
    const int2* __restrict__ epack,
    const float* __restrict__ bias, const float* __restrict__ invdeg,
    const float* __restrict__ aW, const float* __restrict__ ab,
    const float* __restrict__ p, const int* __restrict__ idx,
    const int* __restrict__ labels, float* __restrict__ raw, int M)
{
    int m = (blockIdx.x * blockDim.x + threadIdx.x) >> 5;
    int lane = threadIdx.x & 31;
    if (m >= M) return;
    int node = idx[m];
    const int coff = lane * 8;

    float hv[8];
    gather_row_core(h + coff, rowptr, epack, invdeg, bias, node, lane, hv);
#pragma unroll
    for (int j = 0; j < 8; j++) hv[j] = hv[j] > 0.f ? hv[j] : expm1f(hv[j]);

    // attention logits (columns coff..coff+7 for this lane)
    float lg[5] = {0.f, 0.f, 0.f, 0.f, 0.f};
#pragma unroll
    for (int j = 0; j < 8; j++) {
        int c = coff + j;
#pragma unroll
        for (int k = 0; k < 5; k++) lg[k] += hv[j] * aW[c * 5 + k];
    }
#pragma unroll
    for (int k = 0; k < 5; k++) lg[k] = warp_sum(lg[k]) + ab[k];
    float mx = lg[0];
#pragma unroll
    for (int k = 1; k < 5; k++) mx = fmaxf(mx, lg[k]);
    float wgt[5], s = 0.f;
#pragma unroll
    for (int k = 0; k < 5; k++) { wgt[k] = expf(lg[k] - mx); s += wgt[k]; }
    float inv = 1.f / s;
#pragma unroll
    for (int k = 0; k < 5; k++) wgt[k] *= inv;

    int lab = labels[m];
#pragma unroll
    for (int j = 0; j < 8; j++) {
        int c = coff + j;
        float v = hv[j];
#pragma unroll
        for (int k = 0; k < 5; k++) v += wgt[k] * p[k * DD + c];
        raw[(size_t)m * DD + c] = v;
        atomicAdd(&g_sums[lab * DD + c], v);
    }
    if (lane == 0) atomicAdd(&g_sums[NC * DD + lab], 1.f);
}

__global__ void an_finalize(const float* __restrict__ sums,
                            const float* __restrict__ cnt, float* __restrict__ an)
{
    int c = blockIdx.x;
    int lane = threadIdx.x;
    float invc = 1.f / fmaxf(cnt[c], 1.f);
    float v[8];
    float ss = 0.f;
#pragma unroll
    for (int i = 0; i < 8; i++) {
        v[i] = sums[c * DD + lane + 32 * i] * invc;
        ss += v[i] * v[i];
    }
    ss = warp_sum(ss);
    float innorm = 1.f / fmaxf(sqrtf(ss), 1e-8f);
#pragma unroll
    for (int i = 0; i < 8; i++) an[c * DD + lane + 32 * i] = v[i] * innorm;
}

__global__ void __launch_bounds__(256) cos_softmax(
    const float* __restrict__ raw, const float* __restrict__ an,
    float* __restrict__ out, int M)
{
    __shared__ float sAn[NC * DD];
    for (int i = threadIdx.x; i < NC * DD; i += 256) sAn[i] = an[i];
    __syncthreads();
    int m = (blockIdx.x * blockDim.x + threadIdx.x) >> 5;
    int lane = threadIdx.x & 31;
    if (m >= M) return;
    float rv[8];
    float ss = 0.f;
#pragma unroll
    for (int i = 0; i < 8; i++) {
        rv[i] = raw[(size_t)m * DD + lane + 32 * i];
        ss += rv[i] * rv[i];
    }
    ss = warp_sum(ss);
    float rinv = 1.f / fmaxf(sqrtf(ss), 1e-8f);
    float sim[NC];
#pragma unroll
    for (int c = 0; c < NC; c++) {
        float s = 0.f;
#pragma unroll
        for (int i = 0; i < 8; i++) s += rv[i] * sAn[c * DD + lane + 32 * i];
        sim[c] = warp_sum(s) * rinv;
    }
    if (lane == 0) {
        float mx = sim[0];
#pragma unroll
        for (int c = 1; c < NC; c++) mx = fmaxf(mx, sim[c]);
        float e[NC], s = 0.f;
#pragma unroll
        for (int c = 0; c < NC; c++) { e[c] = expf(sim[c] - mx); s += e[c]; }
        float inv = 1.f / s;
#pragma unroll
        for (int c = 0; c < NC; c++) out[(size_t)m * NC + c] = e[c] * inv;
    }
}

// ---------------------------------------------------------------------------
// Orchestration
// ---------------------------------------------------------------------------
extern "C" void kernel_launch(void* const* d_in, const int* in_sizes, int n_in,
                              void* d_out, int out_size)
{
    const float* x0     = (const float*)d_in[0];
    const int*   src    = (const int*)d_in[1];
    const int*   dst    = (const int*)d_in[2];
    const int*   idx    = (const int*)d_in[3];
    const int*   labels = (const int*)d_in[4];
    const float* W1 = (const float*)d_in[6];
    const float* b1 = (const float*)d_in[7];
    const float* W2 = (const float*)d_in[8];
    const float* b2 = (const float*)d_in[9];
    const float* W3 = (const float*)d_in[10];
    const float* b3 = (const float*)d_in[11];
    const float* cw_in  = (const float*)d_in[12];
    const float* cb_in  = (const float*)d_in[13];
    const float* cw_hid = (const float*)d_in[14];
    const float* cb_hid = (const float*)d_in[15];
    const float* cw_out = (const float*)d_in[16];
    const float* cb_out = (const float*)d_in[17];
    const float* p_list = (const float*)d_in[18];
    const float* aW     = (const float*)d_in[19];
    const float* ab     = (const float*)d_in[20];
    const float* gw2    = (const float*)d_in[21];

    const int N = in_sizes[0] / DD;
    const int E = in_sizes[1];
    const int M = in_sizes[3];
    float* out = (float*)d_out;

    bf16 *bxb, *bx0b, *bhb, *be1b, *be2b;
    uint8_t* bh8;
    float *bdinv, *binvdeg, *braw, *bsums, *ban;
    uint32_t* bwp;
    int *bdegi, *browptr, *bcursor;
    int2* bepack;
    cudaGetSymbolAddress((void**)&bxb,  g_xb);
    cudaGetSymbolAddress((void**)&bx0b, g_x0b);
    cudaGetSymbolAddress((void**)&bhb,  g_hb);
    cudaGetSymbolAddress((void**)&bh8,  g_h8);
    cudaGetSymbolAddress((void**)&be1b, g_e1b);
    cudaGetSymbolAddress((void**)&be2b, g_e2b);
    cudaGetSymbolAddress((void**)&bwp,  g_wp);
    cudaGetSymbolAddress((void**)&bdegi, g_degi);
    cudaGetSymbolAddress((void**)&bdinv, g_dinv);
    cudaGetSymbolAddress((void**)&binvdeg, g_invdeg);
    cudaGetSymbolAddress((void**)&browptr, g_rowptr);
    cudaGetSymbolAddress((void**)&bcursor, g_cursor);
    cudaGetSymbolAddress((void**)&bepack, g_epack);
    cudaGetSymbolAddress((void**)&braw, g_raw);
    cudaGetSymbolAddress((void**)&bsums, g_sums);
    cudaGetSymbolAddress((void**)&ban, g_an);
    float* bcnt = bsums + NC * DD;

    const bool fork = g_si.ok;
    cudaStream_t s2 = fork ? g_si.s2 : (cudaStream_t)0;

    // --- fork: CSR build + bsums clear on side stream ---
    if (fork) {
        cudaEventRecord(g_si.ev1, 0);
        cudaStreamWaitEvent(s2, g_si.ev1, 0);
    }
    cudaMemsetAsync(bdegi, 0, (size_t)N * sizeof(int), s2);
    cudaMemsetAsync(bsums, 0, (NC * DD + 32) * sizeof(float), s2);
    count_deg<<<(E + 255) / 256, 256, 0, s2>>>(dst, bdegi, E);
    finalize_deg<<<(N + 255) / 256, 256, 0, s2>>>(bdegi, bdinv, binvdeg, N);
    scan_rowptr<<<1, 1024, 0, s2>>>(bdegi, browptr, bcursor, N);
    fill_csr<<<(E + 255) / 256, 256, 0, s2>>>(src, dst, bdinv, bcursor, bepack, E);
    if (fork) cudaEventRecord(g_si.ev2, s2);

    // --- main stream: prepack + convert + GEMM chain ---
    prepack_weights<<<dim3(128, 12), 256>>>(W1, W2, W3, cw_in, cw_hid, cw_out, bwp);
    {
        int n4 = N * DD / 4;
        conv_f32_bf16<<<(n4 + 255) / 256, 256>>>(x0, bx0b, n4);
    }

    const dim3 gg((N + 127) / 128, 2);
    const int rowBlocks = (N + 7) / 8;
    const uint32_t* wp1 = bwp;
    const uint32_t* wp2 = bwp + 1 * 32768;
    const uint32_t* wp3 = bwp + 2 * 32768;

    bool joined = false;
    const bf16* cur = bx0b;
    for (int t = 0; t < 3; t++) {
        bf16_gemm<0, 1><<<gg, 256>>>(cur, wp1, nullptr, nullptr, bh8, N);
        if (!joined) {
            if (fork) cudaStreamWaitEvent(0, g_si.ev2, 0);
            joined = true;
        }
        gather_gcn_fp8<0, 0, 0><<<rowBlocks, 256>>>(bh8, browptr, bepack, b1, binvdeg,
                                                    nullptr, nullptr, be1b, N);
        bf16_gemm<0, 1><<<gg, 256>>>(be1b, wp2, nullptr, nullptr, bh8, N);
        gather_gcn_fp8<1, 1, 0><<<rowBlocks, 256>>>(bh8, browptr, bepack, b2, binvdeg,
                                                    be1b, gw2, be2b, N);
        bf16_gemm<1, 0><<<gg, 256>>>(be2b, bwp + (size_t)(3 + t) * 32768, cb_in + t * DD,
                                     nullptr, bhb, N);
        bf16_gemm<1, 0><<<gg, 256>>>(bhb, bwp + (size_t)(6 + t) * 32768, cb_hid + t * DD,
                                     nullptr, be1b, N);
        bf16_gemm<2, 0><<<gg, 256>>>(be1b, bwp + (size_t)(9 + t) * 32768, cb_out + t * DD,
                                     bx0b, bxb, N);
        cur = bxb;
    }

    // final GCN: layers 1,2 full; layer 3 gather restricted to idx rows (fused)
    bf16_gemm<0, 1><<<gg, 256>>>(bxb, wp1, nullptr, nullptr, bh8, N);
    gather_gcn_fp8<0, 0, 1><<<rowBlocks, 256>>>(bh8, browptr, bepack, b1, binvdeg,
                                                nullptr, nullptr, be1b, N);
    bf16_gemm<0, 1><<<gg, 256>>>(be1b, wp2, nullptr, nullptr, bh8, N);
    gather_gcn_fp8<0, 0, 1><<<rowBlocks, 256>>>(bh8, browptr, bepack, b2, binvdeg,
                                                nullptr, nullptr, be2b, N);
    bf16_gemm<0, 1><<<gg, 256>>>(be2b, wp3, nullptr, nullptr, bh8, N);

    gather_embed_proto<<<(M + 7) / 8, 256>>>(bh8, browptr, bepack, b3, binvdeg,
                                             aW, ab, p_list, idx, labels, braw, M);
    an_finalize<<<NC, 32>>>(bsums, bcnt, ban);
    cos_softmax<<<(M + 7) / 8, 256>>>(braw, ban, out, M);
}

// round 17
// speedup vs baseline: 1.1359x; 1.0108x over previous
#include <cuda_runtime.h>
#include <cuda_bf16.h>
#include <cuda_fp16.h>
#include <math.h>
#include <stdint.h>

// ---------------------------------------------------------------------------
// downprompt. R17: ConditionNet re-fused at 64-row tiles (101KB smem ->
// 2 CTAs/SM, fixing R8's 1-CTA/SM failure). Rest = R16: bf16 HMMA GEMMs,
// fp8 HFMA2 gather w/ packed edges, side-stream CSR, final gather at idx
// rows fused with attention+prototypes, dead-e3 eliminated.
// ---------------------------------------------------------------------------

#define DD   256
#define MAXN 20000
#define MAXE 320000
#define MAXM 2048
#define NC   10

typedef __nv_bfloat16 bf16;
typedef __nv_bfloat162 bf162;

__device__ bf16    g_xb [MAXN * DD];
__device__ bf16    g_x0b[MAXN * DD];
__device__ uint8_t g_h8 [MAXN * DD];
__device__ bf16    g_e1b[MAXN * DD];
__device__ bf16    g_e2b[MAXN * DD];
__device__ uint32_t g_wp[12 * 32768];
__device__ int   g_degi[MAXN];
__device__ float g_dinv[MAXN];
__device__ float g_invdeg[MAXN];
__device__ int   g_rowptr[MAXN + 4];
__device__ int   g_cursor[MAXN + 4];
__device__ int2  g_epack[MAXE];
__device__ float g_raw[MAXM * DD];
__device__ float g_sums[NC * DD + 32];
__device__ float g_an[NC * DD];

struct StreamInit {
    cudaStream_t s2 = nullptr;
    cudaEvent_t ev1 = nullptr, ev2 = nullptr;
    bool ok = false;
    StreamInit() {
        ok = (cudaStreamCreateWithFlags(&s2, cudaStreamNonBlocking) == cudaSuccess) &&
             (cudaEventCreateWithFlags(&ev1, cudaEventDisableTiming) == cudaSuccess) &&
             (cudaEventCreateWithFlags(&ev2, cudaEventDisableTiming) == cudaSuccess);
    }
};
static StreamInit g_si;

__device__ __forceinline__ float warp_sum(float v) {
#pragma unroll
    for (int o = 16; o > 0; o >>= 1) v += __shfl_xor_sync(0xffffffffu, v, o);
    return v;
}

__device__ __forceinline__ void mma_bf16(
    float& c0, float& c1, float& c2, float& c3,
    uint32_t a0, uint32_t a1, uint32_t a2, uint32_t a3,
    uint32_t b0, uint32_t b1)
{
    asm volatile(
        "mma.sync.aligned.m16n8k16.row.col.f32.bf16.bf16.f32 "
        "{%0,%1,%2,%3},{%4,%5,%6,%7},{%8,%9},{%0,%1,%2,%3};"
        : "+f"(c0), "+f"(c1), "+f"(c2), "+f"(c3)
        : "r"(a0), "r"(a1), "r"(a2), "r"(a3), "r"(b0), "r"(b1));
}

__device__ __forceinline__ void cp_async16(void* smem_dst, const void* gmem_src, int src_bytes) {
    uint32_t s = (uint32_t)__cvta_generic_to_shared(smem_dst);
    asm volatile("cp.async.cg.shared.global [%0], [%1], 16, %2;"
                 :: "r"(s), "l"(gmem_src), "r"(src_bytes));
}

// ---------------------------------------------------------------------------
// Weight prepack (bf16 k-pair layout)
// ---------------------------------------------------------------------------
__global__ void __launch_bounds__(256) prepack_weights(
    const float* __restrict__ W1, const float* __restrict__ W2,
    const float* __restrict__ W3, const float* __restrict__ cw_in,
    const float* __restrict__ cw_hid, const float* __restrict__ cw_out,
    uint32_t* __restrict__ wp)
{
    int m = blockIdx.y;
    const float* W =
        (m == 0) ? W1 : (m == 1) ? W2 : (m == 2) ? W3 :
        (m < 6) ? cw_in  + (size_t)(m - 3) * 65536 :
        (m < 9) ? cw_hid + (size_t)(m - 6) * 65536 :
                  cw_out + (size_t)(m - 9) * 65536;
    int i = blockIdx.x * 256 + threadIdx.x;
    int k2 = i >> 8, n = i & 255;
    float lo = W[(size_t)(2 * k2) * 256 + n];
    float hi = W[(size_t)(2 * k2 + 1) * 256 + n];
    bf162 p = __floats2bfloat162_rn(lo, hi);
    wp[(size_t)m * 32768 + i] = *(uint32_t*)&p;
}

__global__ void __launch_bounds__(256) conv_f32_bf16(
    const float* __restrict__ in, bf16* __restrict__ out, int n4)
{
    int i = blockIdx.x * blockDim.x + threadIdx.x;
    if (i >= n4) return;
    float4 v = ((const float4*)in)[i];
    bf162 a = __floats2bfloat162_rn(v.x, v.y);
    bf162 b = __floats2bfloat162_rn(v.z, v.w);
    uint2 u;
    u.x = *(uint32_t*)&a;
    u.y = *(uint32_t*)&b;
    ((uint2*)out)[i] = u;
}

// ---------------------------------------------------------------------------
// bf16 GEMM (GCN layers): 128x128 tile, BK=32, 2-stage cp.async, 8 warps.
// EPI 0: plain. OUT8: write e4m3 (gather input), else bf16.
// ---------------------------------------------------------------------------
#define ASB   40
#define BSPW  136

template <int EPI, int OUT8>
__global__ void __launch_bounds__(256) bf16_gemm(
    const bf16* __restrict__ A, const uint32_t* __restrict__ Wp,
    const float* __restrict__ bias, const bf16* __restrict__ extra,
    void* __restrict__ Cv, int N)
{
    __shared__ __align__(16) bf16     As[2][128 * ASB];
    __shared__ __align__(16) uint32_t Bsp[2][16 * BSPW];

    const int tid  = threadIdx.x;
    const int lane = tid & 31;
    const int wid  = tid >> 5;
    const int wm   = wid & 3;
    const int wn   = wid >> 2;
    const int rowBase = blockIdx.x * 128;
    const int colBase = blockIdx.y * 128;
    const int lq = lane >> 2;
    const int lr = lane & 3;

    float acc[2][8][4];
#pragma unroll
    for (int mt = 0; mt < 2; mt++)
#pragma unroll
        for (int nt = 0; nt < 8; nt++)
#pragma unroll
            for (int i = 0; i < 4; i++) acc[mt][nt][i] = 0.f;

    auto loadTile = [&](int k0, int st) {
#pragma unroll
        for (int i = 0; i < 2; i++) {
            int ch = tid + i * 256;
            int r  = ch >> 2;
            int kc = (ch & 3) * 8;
            int grow = rowBase + r;
            int ok = (grow < N) ? 16 : 0;
            int crow = (grow < N) ? grow : (N - 1);
            cp_async16(&As[st][r * ASB + kc], A + (size_t)crow * 256 + k0 + kc, ok);
        }
#pragma unroll
        for (int i = 0; i < 2; i++) {
            int ch = tid + i * 256;
            int k2 = ch >> 5;
            int nc = (ch & 31) * 4;
            cp_async16(&Bsp[st][k2 * BSPW + nc],
                       Wp + (size_t)(k0 / 2 + k2) * 256 + colBase + nc, 16);
        }
        asm volatile("cp.async.commit_group;");
    };

    loadTile(0, 0);
#pragma unroll
    for (int it = 0; it < 8; it++) {
        if (it < 7) {
            loadTile((it + 1) * 32, (it + 1) & 1);
            asm volatile("cp.async.wait_group 1;");
        } else {
            asm volatile("cp.async.wait_group 0;");
        }
        __syncthreads();
        const bf16* As_ = As[it & 1];
        const uint32_t* Bp = Bsp[it & 1];
#pragma unroll
        for (int ks = 0; ks < 2; ks++) {
            uint32_t a[2][4];
#pragma unroll
            for (int mt = 0; mt < 2; mt++) {
                int r = wm * 32 + mt * 16 + lq;
                const uint32_t* ar0 = (const uint32_t*)(As_ + r * ASB) + ks * 8 + lr;
                const uint32_t* ar1 = (const uint32_t*)(As_ + (r + 8) * ASB) + ks * 8 + lr;
                a[mt][0] = ar0[0];
                a[mt][1] = ar1[0];
                a[mt][2] = ar0[4];
                a[mt][3] = ar1[4];
            }
            uint32_t b0[8], b1[8];
#pragma unroll
            for (int nt = 0; nt < 8; nt++) {
                int n = wn * 64 + nt * 8 + lq;
                b0[nt] = Bp[(ks * 8 + lr) * BSPW + n];
                b1[nt] = Bp[(ks * 8 + lr + 4) * BSPW + n];
            }
#pragma unroll
            for (int mt = 0; mt < 2; mt++)
#pragma unroll
                for (int nt = 0; nt < 8; nt++)
                    mma_bf16(acc[mt][nt][0], acc[mt][nt][1], acc[mt][nt][2], acc[mt][nt][3],
                             a[mt][0], a[mt][1], a[mt][2], a[mt][3], b0[nt], b1[nt]);
        }
        __syncthreads();
    }

#pragma unroll
    for (int mt = 0; mt < 2; mt++) {
#pragma unroll
        for (int rr = 0; rr < 2; rr++) {
            int row = rowBase + wm * 32 + mt * 16 + lq + rr * 8;
            if (row >= N) continue;
#pragma unroll
            for (int nt = 0; nt < 8; nt++) {
                int col = colBase + wn * 64 + nt * 8 + 2 * lr;
                float v0 = acc[mt][nt][rr * 2 + 0];
                float v1 = acc[mt][nt][rr * 2 + 1];
                if (EPI >= 1) { v0 += bias[col]; v1 += bias[col + 1]; }
                if (EPI == 1) {
                    v0 = v0 > 0.f ? v0 : expm1f(v0);
                    v1 = v1 > 0.f ? v1 : expm1f(v1);
                }
                if (EPI == 2) {
                    float2 ex = __bfloat1622float2(
                        *(const bf162*)(extra + (size_t)row * 256 + col));
                    v0 *= ex.x; v1 *= ex.y;
                }
                if (OUT8) {
                    unsigned short p;
                    asm("cvt.rn.satfinite.e4m3x2.f32 %0, %1, %2;"
                        : "=h"(p) : "f"(v1), "f"(v0));
                    *(unsigned short*)((uint8_t*)Cv + (size_t)row * 256 + col) = p;
                } else {
                    *(bf162*)((bf16*)Cv + (size_t)row * 256 + col) =
                        __floats2bfloat162_rn(v0, v1);
                }
            }
        }
    }
}

// ---------------------------------------------------------------------------
// cn_fused64: 3 chained CN GEMMs on a 64x256 tile; 2 CTAs/SM.
// prompt = Wout(elu(Whid(elu(Win x + bin)) + bhid)) + bout; x_new = prompt*x0
// 8 warps (2M x 4N), acc[2][8][4]; A ping-pong in smem, W double-buffered.
// ---------------------------------------------------------------------------
#define HST 264   // bf16 per A row (256 + 8 pad); uint32 stride 132
#define BST 264   // uint32 per B k2-row (256 + 8 pad)
#define CN_SMEM (2 * 64 * HST * 2 + 2 * 16 * BST * 4)   // 101376 B

__global__ void __launch_bounds__(256, 2) cn_fused64(
    const bf16* __restrict__ X, const uint32_t* __restrict__ Win,
    const uint32_t* __restrict__ Whid, const uint32_t* __restrict__ Wout,
    const float* __restrict__ bin, const float* __restrict__ bhid,
    const float* __restrict__ bout, const bf16* __restrict__ X0,
    bf16* __restrict__ OutX, int N)
{
    extern __shared__ char sm[];
    bf16* hA0 = (bf16*)sm;
    bf16* hA1 = (bf16*)(sm + 64 * HST * 2);
    uint32_t* Bq0 = (uint32_t*)(sm + 2 * 64 * HST * 2);
    uint32_t* Bq1 = Bq0 + 16 * BST;

    const int tid  = threadIdx.x;
    const int lane = tid & 31;
    const int wid  = tid >> 5;
    const int wm   = wid & 1;        // 2 M groups of 32 rows
    const int wn   = wid >> 1;       // 4 N groups of 64 cols
    const int rowBase = blockIdx.x * 64;
    const int lq = lane >> 2;
    const int lr = lane & 3;

    // X tile: 64 rows x 256 bf16 = 2048 16B chunks, 8 per thread (async)
#pragma unroll
    for (int i = 0; i < 8; i++) {
        int ch = tid + i * 256;
        int r  = ch >> 5;            // 0..63
        int c  = (ch & 31) * 8;      // bf16 col
        int grow = rowBase + r;
        int ok = (grow < N) ? 16 : 0;
        int crow = (grow < N) ? grow : (N - 1);
        cp_async16(hA0 + r * HST + c, X + (size_t)crow * 256 + c, ok);
    }

    const uint32_t* Ws[3] = {Win, Whid, Wout};
    bf16* hbuf[2] = {hA0, hA1};
    uint32_t* Bqs[2] = {Bq0, Bq1};

#pragma unroll 1
    for (int l = 0; l < 3; l++) {
        const bf16* Asrc = hbuf[l & 1];
        const uint32_t* Wp = Ws[l];

        // first B chunk: 16 k2-rows x 256 u32 = 1024 chunks, 4/thread
#pragma unroll
        for (int i = 0; i < 4; i++) {
            int ch = tid + i * 256;
            int k2 = ch >> 6;
            int nc = (ch & 63) * 4;
            cp_async16(Bq0 + k2 * BST + nc, Wp + (size_t)k2 * 256 + nc, 16);
        }
        asm volatile("cp.async.commit_group;");

        float acc[2][8][4];
#pragma unroll
        for (int mt = 0; mt < 2; mt++)
#pragma unroll
            for (int nt = 0; nt < 8; nt++)
#pragma unroll
                for (int i = 0; i < 4; i++) acc[mt][nt][i] = 0.f;

#pragma unroll
        for (int it = 0; it < 8; it++) {
            if (it < 7) {
                uint32_t* Bd = Bqs[(it + 1) & 1];
                int kb = (it + 1) * 16;
#pragma unroll
                for (int i = 0; i < 4; i++) {
                    int ch = tid + i * 256;
                    int k2 = ch >> 6;
                    int nc = (ch & 63) * 4;
                    cp_async16(Bd + k2 * BST + nc, Wp + (size_t)(kb + k2) * 256 + nc, 16);
                }
                asm volatile("cp.async.commit_group;");
                asm volatile("cp.async.wait_group 1;");
            } else {
                asm volatile("cp.async.wait_group 0;");
            }
            __syncthreads();
            const uint32_t* Bp = Bqs[it & 1];
            const int ku = it * 16;
#pragma unroll
            for (int ks = 0; ks < 2; ks++) {
                uint32_t a[2][4];
#pragma unroll
                for (int mt = 0; mt < 2; mt++) {
                    int r = wm * 32 + mt * 16 + lq;
                    const uint32_t* ar0 = (const uint32_t*)(Asrc + r * HST) + ku + ks * 8 + lr;
                    const uint32_t* ar1 = (const uint32_t*)(Asrc + (r + 8) * HST) + ku + ks * 8 + lr;
                    a[mt][0] = ar0[0];
                    a[mt][1] = ar1[0];
                    a[mt][2] = ar0[4];
                    a[mt][3] = ar1[4];
                }
                uint32_t b0[8], b1[8];
#pragma unroll
                for (int nt = 0; nt < 8; nt++) {
                    int n = wn * 64 + nt * 8 + lq;
                    b0[nt] = Bp[(ks * 8 + lr) * BST + n];
                    b1[nt] = Bp[(ks * 8 + lr + 4) * BST + n];
                }
#pragma unroll
                for (int mt = 0; mt < 2; mt++)
#pragma unroll
                    for (int nt = 0; nt < 8; nt++)
                        mma_bf16(acc[mt][nt][0], acc[mt][nt][1], acc[mt][nt][2], acc[mt][nt][3],
                                 a[mt][0], a[mt][1], a[mt][2], a[mt][3], b0[nt], b1[nt]);
            }
            __syncthreads();
        }

        if (l < 2) {
            bf16* dst = hbuf[(l + 1) & 1];
            const float* bias = (l == 0) ? bin : bhid;
#pragma unroll
            for (int mt = 0; mt < 2; mt++) {
#pragma unroll
                for (int rr = 0; rr < 2; rr++) {
                    int r = wm * 32 + mt * 16 + lq + rr * 8;
#pragma unroll
                    for (int nt = 0; nt < 8; nt++) {
                        int col = wn * 64 + nt * 8 + 2 * lr;
                        float v0 = acc[mt][nt][rr * 2 + 0] + bias[col];
                        float v1 = acc[mt][nt][rr * 2 + 1] + bias[col + 1];
                        v0 = v0 > 0.f ? v0 : expm1f(v0);
                        v1 = v1 > 0.f ? v1 : expm1f(v1);
                        *(bf162*)(dst + r * HST + col) = __floats2bfloat162_rn(v0, v1);
                    }
                }
            }
            __syncthreads();
        } else {
#pragma unroll
            for (int mt = 0; mt < 2; mt++) {
#pragma unroll
                for (int rr = 0; rr < 2; rr++) {
                    int row = rowBase + wm * 32 + mt * 16 + lq + rr * 8;
                    if (row >= N) continue;
#pragma unroll
                    for (int nt = 0; nt < 8; nt++) {
                        int col = wn * 64 + nt * 8 + 2 * lr;
                        float v0 = acc[mt][nt][rr * 2 + 0] + bout[col];
                        float v1 = acc[mt][nt][rr * 2 + 1] + bout[col + 1];
                        float2 ex = __bfloat1622float2(
                            *(const bf162*)(X0 + (size_t)row * 256 + col));
                        v0 *= ex.x; v1 *= ex.y;
                        *(bf162*)(OutX + (size_t)row * 256 + col) =
                            __floats2bfloat162_rn(v0, v1);
                    }
                }
            }
        }
    }
}

// ---------------------------------------------------------------------------
// CSR build (side stream)
// ---------------------------------------------------------------------------
__global__ void count_deg(const int* __restrict__ dst, int* __restrict__ degi, int E) {
    int e = blockIdx.x * blockDim.x + threadIdx.x;
    if (e < E) atomicAdd(&degi[dst[e]], 1);
}

__global__ void finalize_deg(const int* __restrict__ degi, float* __restrict__ dinv,
                             float* __restrict__ invdeg, int N) {
    int i = blockIdx.x * blockDim.x + threadIdx.x;
    if (i < N) {
        float d = (float)degi[i] + 1.f;
        dinv[i] = rsqrtf(d);
        invdeg[i] = 1.f / d;
    }
}

__global__ void __launch_bounds__(1024) scan_rowptr(
    const int* __restrict__ degi, int* __restrict__ rowptr, int* __restrict__ cursor, int N)
{
    __shared__ int warpTot[32];
    const int t = threadIdx.x;
    const int lane = t & 31;
    const int warp = t >> 5;
    const int n4 = N >> 2;
    const int per4 = (n4 + 1023) >> 10;
    const int b4 = t * per4;
    const int e4 = min(b4 + per4, n4);
    const int cnt = max(e4 - b4, 0);

    int4 v[8];
    int sum = 0;
    for (int i = 0; i < cnt; i++) {
        v[i] = ((const int4*)degi)[b4 + i];
        sum += v[i].x + v[i].y + v[i].z + v[i].w;
    }

    int inc = sum;
#pragma unroll
    for (int off = 1; off < 32; off <<= 1) {
        int x = __shfl_up_sync(0xffffffffu, inc, off);
        if (lane >= off) inc += x;
    }
    if (lane == 31) warpTot[warp] = inc;
    __syncthreads();
    if (warp == 0) {
        int wv = warpTot[lane];
        int winc = wv;
#pragma unroll
        for (int off = 1; off < 32; off <<= 1) {
            int x = __shfl_up_sync(0xffffffffu, winc, off);
            if (lane >= off) winc += x;
        }
        warpTot[lane] = winc - wv;
    }
    __syncthreads();
    int run = warpTot[warp] + inc - sum;

    for (int i = 0; i < cnt; i++) {
        int base4 = b4 + i;
        int d0 = v[i].x, d1 = v[i].y, d2 = v[i].z, d3 = v[i].w;
        int r0 = run, r1 = r0 + d0, r2 = r1 + d1, r3 = r2 + d2;
        run = r3 + d3;
        int4 rp = make_int4(r0, r1, r2, r3);
        ((int4*)rowptr)[base4] = rp;
        ((int4*)cursor)[base4] = rp;
    }
    if (t == 1023) {
        int run2 = run;
        for (int i = n4 * 4; i < N; i++) {
            rowptr[i] = run2;
            cursor[i] = run2;
            run2 += degi[i];
        }
        rowptr[N] = run2;
    }
}

__global__ void fill_csr(const int* __restrict__ src, const int* __restrict__ dst,
                         const float* __restrict__ dinv, int* __restrict__ cursor,
                         int2* __restrict__ epack, int E)
{
    int e = blockIdx.x * blockDim.x + threadIdx.x;
    if (e >= E) return;
    int s = src[e], d = dst[e];
    int slot = atomicAdd(&cursor[d], 1);
    float cf = dinv[s] * dinv[d];
    __half2 c2 = __float2half2_rn(cf);
    epack[slot] = make_int2(s * DD, (int)*(uint32_t*)&c2);
}

// ---------------------------------------------------------------------------
// Gather SpMM (fp8 in, bf16 out), half2 HFMA2 accumulation, packed edges.
// ---------------------------------------------------------------------------
__device__ __forceinline__ void accum_h2(__half2* acc, uint2 v, __half2 c2) {
    uint32_t h0, h1, h2, h3;
    asm("cvt.rn.f16x2.e4m3x2 %0, %1;" : "=r"(h0) : "h"((unsigned short)(v.x & 0xffffu)));
    asm("cvt.rn.f16x2.e4m3x2 %0, %1;" : "=r"(h1) : "h"((unsigned short)(v.x >> 16)));
    asm("cvt.rn.f16x2.e4m3x2 %0, %1;" : "=r"(h2) : "h"((unsigned short)(v.y & 0xffffu)));
    asm("cvt.rn.f16x2.e4m3x2 %0, %1;" : "=r"(h3) : "h"((unsigned short)(v.y >> 16)));
    acc[0] = __hfma2(*(__half2*)&h0, c2, acc[0]);
    acc[1] = __hfma2(*(__half2*)&h1, c2, acc[1]);
    acc[2] = __hfma2(*(__half2*)&h2, c2, acc[2]);
    acc[3] = __hfma2(*(__half2*)&h3, c2, acc[3]);
}

__device__ __forceinline__ void accum8_bf16(float* acc, uint4 v, float c) {
    bf162* p = (bf162*)&v;
#pragma unroll
    for (int j = 0; j < 4; j++) {
        float2 f = __bfloat1622float2(p[j]);
        acc[2 * j]     += f.x * c;
        acc[2 * j + 1] += f.y * c;
    }
}

__device__ __forceinline__ void gather_row_core(
    const uint8_t* __restrict__ hbase, const int* __restrict__ rowptr,
    const int2* __restrict__ epack, const float* __restrict__ invdeg,
    const float* __restrict__ bias, int d, int lane, float* acc)
{
    const int eBeg = rowptr[d];
    const int eEnd = rowptr[d + 1];

    __half2 hacc[4];
    __half2 hz = __float2half2_rn(0.f);
#pragma unroll
    for (int j = 0; j < 4; j++) hacc[j] = hz;

    int e = eBeg;
    for (; e + 7 < eEnd; e += 8) {
        int2  p[8];
        uint2 v[8];
#pragma unroll
        for (int j = 0; j < 8; j++) p[j] = epack[e + j];
#pragma unroll
        for (int j = 0; j < 8; j++) v[j] = *(const uint2*)(hbase + p[j].x);
#pragma unroll
        for (int j = 0; j < 8; j++) accum_h2(hacc, v[j], *(__half2*)&p[j].y);
    }
    for (; e + 1 < eEnd; e += 2) {
        int2 p0 = epack[e], p1 = epack[e + 1];
        uint2 v0 = *(const uint2*)(hbase + p0.x);
        uint2 v1 = *(const uint2*)(hbase + p1.x);
        accum_h2(hacc, v0, *(__half2*)&p0.y);
        accum_h2(hacc, v1, *(__half2*)&p1.y);
    }
    if (e < eEnd) {
        int2 p0 = epack[e];
        uint2 v0 = *(const uint2*)(hbase + p0.x);
        accum_h2(hacc, v0, *(__half2*)&p0.y);
    }

    uint2 vs = *(const uint2*)(hbase + d * DD);
    accum_h2(hacc, vs, __float2half2_rn(invdeg[d]));

#pragma unroll
    for (int j = 0; j < 4; j++) {
        float2 f = __half22float2(hacc[j]);
        acc[2 * j] = f.x;
        acc[2 * j + 1] = f.y;
    }
    float4 b0 = ((const float4*)bias)[lane * 2];
    float4 b1 = ((const float4*)bias)[lane * 2 + 1];
    acc[0] += b0.x; acc[1] += b0.y; acc[2] += b0.z; acc[3] += b0.w;
    acc[4] += b1.x; acc[5] += b1.y; acc[6] += b1.z; acc[7] += b1.w;
}

template <int RES, int SCALE, int ELU>
__global__ void __launch_bounds__(256) gather_gcn_fp8(
    const uint8_t* __restrict__ h, const int* __restrict__ rowptr,
    const int2* __restrict__ epack,
    const float* __restrict__ bias, const float* __restrict__ invdeg,
    const bf16* __restrict__ res, const float* __restrict__ scale_ptr,
    bf16* __restrict__ out, int N)
{
    int d = (blockIdx.x * blockDim.x + threadIdx.x) >> 5;
    int lane = threadIdx.x & 31;
    if (d >= N) return;
    const int coff = lane * 8;

    float acc[8];
    gather_row_core(h + coff, rowptr, epack, invdeg, bias, d, lane, acc);

    if (RES) {
        uint4 rv = *(const uint4*)(res + (size_t)d * DD + coff);
        accum8_bf16(acc, rv, 1.f);
    }
    if (SCALE) {
        float sc = scale_ptr[0];
#pragma unroll
        for (int j = 0; j < 8; j++) acc[j] *= sc;
    }
    if (ELU) {
#pragma unroll
        for (int j = 0; j < 8; j++) acc[j] = acc[j] > 0.f ? acc[j] : expm1f(acc[j]);
    }
    uint4 ov;
    bf162* op = (bf162*)&ov;
#pragma unroll
    for (int j = 0; j < 4; j++) op[j] = __floats2bfloat162_rn(acc[2 * j], acc[2 * j + 1]);
    *(uint4*)(out + (size_t)d * DD + coff) = ov;
}

// ---------------------------------------------------------------------------
// Fused FINAL layer: gather gcn3 at idx rows + ELU + attention + proto accum.
// ---------------------------------------------------------------------------
__global__ void __launch_bounds__(256) gather_embed_proto(
    const uint8_t* __restrict__ h, const int* __restrict__ rowptr,
    const int2* __restrict__ epack,
    const float* __restrict__ bias, const float* __restrict__ invdeg,
    const float* __restrict__ aW, const float* __restrict__ ab,
    const float* __restrict__ p, const int* __restrict__ idx,
    const int* __restrict__ labels, float* __restrict__ raw, int M)
{
    int m = (blockIdx.x * blockDim.x + threadIdx.x) >> 5;
    int lane = threadIdx.x & 31;
    if (m >= M) return;
    int node = idx[m];
    const int coff = lane * 8;

    float hv[8];
    gather_row_core(h + coff, rowptr, epack, invdeg, bias, node, lane, hv);
#pragma unroll
    for (int j = 0; j < 8; j++) hv[j] = hv[j] > 0.f ? hv[j] : expm1f(hv[j]);

    float lg[5] = {0.f, 0.f, 0.f, 0.f, 0.f};
#pragma unroll
    for (int j = 0; j < 8; j++) {
        int c = coff + j;
#pragma unroll
        for (int k = 0; k < 5; k++) lg[k] += hv[j] * aW[c * 5 + k];
    }
#pragma unroll
    for (int k = 0; k < 5; k++) lg[k] = warp_sum(lg[k]) + ab[k];
    float mx = lg[0];
#pragma unroll
    for (int k = 1; k < 5; k++) mx = fmaxf(mx, lg[k]);
    float wgt[5], s = 0.f;
#pragma unroll
    for (int k = 0; k < 5; k++) { wgt[k] = expf(lg[k] - mx); s += wgt[k]; }
    float inv = 1.f / s;
#pragma unroll
    for (int k = 0; k < 5; k++) wgt[k] *= inv;

    int lab = labels[m];
#pragma unroll
    for (int j = 0; j < 8; j++) {
        int c = coff + j;
        float v = hv[j];
#pragma unroll
        for (int k = 0; k < 5; k++) v += wgt[k] * p[k * DD + c];
        raw[(size_t)m * DD + c] = v;
        atomicAdd(&g_sums[lab * DD + c], v);
    }
    if (lane == 0) atomicAdd(&g_sums[NC * DD + lab], 1.f);
}

__global__ void an_finalize(const float* __restrict__ sums,
                            const float* __restrict__ cnt, float* __restrict__ an)
{
    int c = blockIdx.x;
    int lane = threadIdx.x;
    float invc = 1.f / fmaxf(cnt[c], 1.f);
    float v[8];
    float ss = 0.f;
#pragma unroll
    for (int i = 0; i < 8; i++) {
        v[i] = sums[c * DD + lane + 32 * i] * invc;
        ss += v[i] * v[i];
    }
    ss = warp_sum(ss);
    float innorm = 1.f / fmaxf(sqrtf(ss), 1e-8f);
#pragma unroll
    for (int i = 0; i < 8; i++) an[c * DD + lane + 32 * i] = v[i] * innorm;
}

__global__ void __launch_bounds__(256) cos_softmax(
    const float* __restrict__ raw, const float* __restrict__ an,
    float* __restrict__ out, int M)
{
    __shared__ float sAn[NC * DD];
    for (int i = threadIdx.x; i < NC * DD; i += 256) sAn[i] = an[i];
    __syncthreads();
    int m = (blockIdx.x * blockDim.x + threadIdx.x) >> 5;
    int lane = threadIdx.x & 31;
    if (m >= M) return;
    float rv[8];
    float ss = 0.f;
#pragma unroll
    for (int i = 0; i < 8; i++) {
        rv[i] = raw[(size_t)m * DD + lane + 32 * i];
        ss += rv[i] * rv[i];
    }
    ss = warp_sum(ss);
    float rinv = 1.f / fmaxf(sqrtf(ss), 1e-8f);
    float sim[NC];
#pragma unroll
    for (int c = 0; c < NC; c++) {
        float s = 0.f;
#pragma unroll
        for (int i = 0; i < 8; i++) s += rv[i] * sAn[c * DD + lane + 32 * i];
        sim[c] = warp_sum(s) * rinv;
    }
    if (lane == 0) {
        float mx = sim[0];
#pragma unroll
        for (int c = 1; c < NC; c++) mx = fmaxf(mx, sim[c]);
        float e[NC], s = 0.f;
#pragma unroll
        for (int c = 0; c < NC; c++) { e[c] = expf(sim[c] - mx); s += e[c]; }
        float inv = 1.f / s;
#pragma unroll
        for (int c = 0; c < NC; c++) out[(size_t)m * NC + c] = e[c] * inv;
    }
}

// ---------------------------------------------------------------------------
// Orchestration
// ---------------------------------------------------------------------------
extern "C" void kernel_launch(void* const* d_in, const int* in_sizes, int n_in,
                              void* d_out, int out_size)
{
    const float* x0     = (const float*)d_in[0];
    const int*   src    = (const int*)d_in[1];
    const int*   dst    = (const int*)d_in[2];
    const int*   idx    = (const int*)d_in[3];
    const int*   labels = (const int*)d_in[4];
    const float* W1 = (const float*)d_in[6];
    const float* b1 = (const float*)d_in[7];
    const float* W2 = (const float*)d_in[8];
    const float* b2 = (const float*)d_in[9];
    const float* W3 = (const float*)d_in[10];
    const float* b3 = (const float*)d_in[11];
    const float* cw_in  = (const float*)d_in[12];
    const float* cb_in  = (const float*)d_in[13];
    const float* cw_hid = (const float*)d_in[14];
    const float* cb_hid = (const float*)d_in[15];
    const float* cw_out = (const float*)d_in[16];
    const float* cb_out = (const float*)d_in[17];
    const float* p_list = (const float*)d_in[18];
    const float* aW     = (const float*)d_in[19];
    const float* ab     = (const float*)d_in[20];
    const float* gw2    = (const float*)d_in[21];

    const int N = in_sizes[0] / DD;
    const int E = in_sizes[1];
    const int M = in_sizes[3];
    float* out = (float*)d_out;

    bf16 *bxb, *bx0b, *be1b, *be2b;
    uint8_t* bh8;
    float *bdinv, *binvdeg, *braw, *bsums, *ban;
    uint32_t* bwp;
    int *bdegi, *browptr, *bcursor;
    int2* bepack;
    cudaGetSymbolAddress((void**)&bxb,  g_xb);
    cudaGetSymbolAddress((void**)&bx0b, g_x0b);
    cudaGetSymbolAddress((void**)&bh8,  g_h8);
    cudaGetSymbolAddress((void**)&be1b, g_e1b);
    cudaGetSymbolAddress((void**)&be2b, g_e2b);
    cudaGetSymbolAddress((void**)&bwp,  g_wp);
    cudaGetSymbolAddress((void**)&bdegi, g_degi);
    cudaGetSymbolAddress((void**)&bdinv, g_dinv);
    cudaGetSymbolAddress((void**)&binvdeg, g_invdeg);
    cudaGetSymbolAddress((void**)&browptr, g_rowptr);
    cudaGetSymbolAddress((void**)&bcursor, g_cursor);
    cudaGetSymbolAddress((void**)&bepack, g_epack);
    cudaGetSymbolAddress((void**)&braw, g_raw);
    cudaGetSymbolAddress((void**)&bsums, g_sums);
    cudaGetSymbolAddress((void**)&ban, g_an);
    float* bcnt = bsums + NC * DD;

    cudaFuncSetAttribute(cn_fused64, cudaFuncAttributeMaxDynamicSharedMemorySize, CN_SMEM);

    const bool fork = g_si.ok;
    cudaStream_t s2 = fork ? g_si.s2 : (cudaStream_t)0;

    // --- fork: CSR build + bsums clear on side stream ---
    if (fork) {
        cudaEventRecord(g_si.ev1, 0);
        cudaStreamWaitEvent(s2, g_si.ev1, 0);
    }
    cudaMemsetAsync(bdegi, 0, (size_t)N * sizeof(int), s2);
    cudaMemsetAsync(bsums, 0, (NC * DD + 32) * sizeof(float), s2);
    count_deg<<<(E + 255) / 256, 256, 0, s2>>>(dst, bdegi, E);
    finalize_deg<<<(N + 255) / 256, 256, 0, s2>>>(bdegi, bdinv, binvdeg, N);
    scan_rowptr<<<1, 1024, 0, s2>>>(bdegi, browptr, bcursor, N);
    fill_csr<<<(E + 255) / 256, 256, 0, s2>>>(src, dst, bdinv, bcursor, bepack, E);
    if (fork) cudaEventRecord(g_si.ev2, s2);

    // --- main stream ---
    prepack_weights<<<dim3(128, 12), 256>>>(W1, W2, W3, cw_in, cw_hid, cw_out, bwp);
    {
        int n4 = N * DD / 4;
        conv_f32_bf16<<<(n4 + 255) / 256, 256>>>(x0, bx0b, n4);
    }

    const dim3 gg((N + 127) / 128, 2);
    const int cnBlocks = (N + 63) / 64;
    const int rowBlocks = (N + 7) / 8;
    const uint32_t* wp1 = bwp;
    const uint32_t* wp2 = bwp + 1 * 32768;
    const uint32_t* wp3 = bwp + 2 * 32768;

    bool joined = false;
    const bf16* cur = bx0b;
    for (int t = 0; t < 3; t++) {
        bf16_gemm<0, 1><<<gg, 256>>>(cur, wp1, nullptr, nullptr, bh8, N);
        if (!joined) {
            if (fork) cudaStreamWaitEvent(0, g_si.ev2, 0);
            joined = true;
        }
        gather_gcn_fp8<0, 0, 0><<<rowBlocks, 256>>>(bh8, browptr, bepack, b1, binvdeg,
                                                    nullptr, nullptr, be1b, N);
        bf16_gemm<0, 1><<<gg, 256>>>(be1b, wp2, nullptr, nullptr, bh8, N);
        gather_gcn_fp8<1, 1, 0><<<rowBlocks, 256>>>(bh8, browptr, bepack, b2, binvdeg,
                                                    be1b, gw2, be2b, N);
        cn_fused64<<<cnBlocks, 256, CN_SMEM>>>(
            be2b,
            bwp + (size_t)(3 + t) * 32768,
            bwp + (size_t)(6 + t) * 32768,
            bwp + (size_t)(9 + t) * 32768,
            cb_in + t * DD, cb_hid + t * DD, cb_out + t * DD,
            bx0b, bxb, N);
        cur = bxb;
    }

    // final GCN: layers 1,2 full; layer 3 gather at idx rows (fused)
    bf16_gemm<0, 1><<<gg, 256>>>(bxb, wp1, nullptr, nullptr, bh8, N);
    gather_gcn_fp8<0, 0, 1><<<rowBlocks, 256>>>(bh8, browptr, bepack, b1, binvdeg,
                                                nullptr, nullptr, be1b, N);
    bf16_gemm<0, 1><<<gg, 256>>>(be1b, wp2, nullptr, nullptr, bh8, N);
    gather_gcn_fp8<0, 0, 1><<<rowBlocks, 256>>>(bh8, browptr, bepack, b2, binvdeg,
                                                nullptr, nullptr, be2b, N);
    bf16_gemm<0, 1><<<gg, 256>>>(be2b, wp3, nullptr, nullptr, bh8, N);

    gather_embed_proto<<<(M + 7) / 8, 256>>>(bh8, browptr, bepack, b3, binvdeg,
                                             aW, ab, p_list, idx, labels, braw, M);
    an_finalize<<<NC, 32>>>(bsums, bcnt, ban);
    cos_softmax<<<(M + 7) / 8, 256>>>(braw, ban, out, M);
}